// round 15
// baseline (speedup 1.0000x reference)
#include <cuda_runtime.h>
#include <cuda_bf16.h>

#define DD 64
#define NEDGE 200000
#define NC5 30000
#define SS5 5
#define NC6 30000
#define SS6 6
#define R5 (NC5*SS5)
#define R6 (NC6*SS6)

typedef unsigned long long u64;
typedef unsigned int u32;

// ---------------- packed f32x2 helpers (Blackwell) ----------------
__device__ __forceinline__ u64 pk(float v) {
    u64 r; asm("mov.b64 %0, {%1, %1};" : "=l"(r) : "f"(v)); return r;
}
__device__ __forceinline__ void fma2(u64& d, u64 a, u64 b) {
    asm("fma.rn.f32x2 %0, %1, %2, %0;" : "+l"(d) : "l"(a), "l"(b));
}
__device__ __forceinline__ float2 up(u64 v) {
    float2 r; asm("mov.b64 {%0, %1}, %2;" : "=f"(r.x), "=f"(r.y) : "l"(v)); return r;
}

// ---------------- bf16 split helpers ----------------
__device__ __forceinline__ u64 split4(float x, float y) {
    __nv_bfloat16 bx = __float2bfloat16_rn(x), by = __float2bfloat16_rn(y);
    float fx = __bfloat162float(bx), fy = __bfloat162float(by);
    __nv_bfloat16 cx = __float2bfloat16_rn(x - fx), cy = __float2bfloat16_rn(y - fy);
    u32 hi = ((u32)(*(unsigned short*)&by) << 16) | *(unsigned short*)&bx;
    u32 lo = ((u32)(*(unsigned short*)&cy) << 16) | *(unsigned short*)&cx;
    return ((u64)lo << 32) | hi;
}
__device__ __forceinline__ void mma_bf16(float d[4], u32 a0, u32 a1, u32 a2, u32 a3,
                                         u32 b0, u32 b1) {
    asm volatile(
        "mma.sync.aligned.m16n8k16.row.col.f32.bf16.bf16.f32 "
        "{%0,%1,%2,%3},{%4,%5,%6,%7},{%8,%9},{%0,%1,%2,%3};"
        : "+f"(d[0]), "+f"(d[1]), "+f"(d[2]), "+f"(d[3])
        : "r"(a0), "r"(a1), "r"(a2), "r"(a3), "r"(b0), "r"(b1));
}

// ---------------- scratch ----------------
__device__ float g_x5[R5*DD];
__device__ float g_x6[R6*DD];
__device__ float g_sB5[NC5*128];
__device__ float g_sB6[NC6*128];
__device__ float g_A5[64*128];
__device__ float g_B5[64*128];
__device__ float g_c5[128];
__device__ float g_A6[64*128];
__device__ float g_B6[64*128];
__device__ float g_c6[128];

// ---------------- weight folding ----------------
__global__ __launch_bounds__(128)
void fold_all_kernel(const float* __restrict__ Wc1, const float* __restrict__ bc1,
                     const float* __restrict__ Wid5, const float* __restrict__ Wsum5,
                     const float* __restrict__ bab5,
                     const float* __restrict__ Wid6, const float* __restrict__ Wsum6,
                     const float* __restrict__ bab6,
                     float* __restrict__ A5, float* __restrict__ B5, float* __restrict__ c5,
                     float* __restrict__ A6, float* __restrict__ B6, float* __restrict__ c6)
{
    int b = blockIdx.x;
    int sz = b / 65;
    int r  = b % 65;
    const float* Wid  = sz ? Wid6  : Wid5;
    const float* Wsum = sz ? Wsum6 : Wsum5;
    const float* bab  = sz ? bab6  : bab5;
    float* A = sz ? A6 : A5;
    float* B = sz ? B6 : B5;
    float* c = sz ? c6 : c5;

    __shared__ float wa[256], wb[256];
    int j = threadIdx.x;
    if (r < 64) {
        wa[j]       = Wid[r*256 + j];
        wa[j + 128] = Wid[r*256 + 128 + j];
        wb[j]       = Wsum[r*256 + j];
        wb[j + 128] = Wsum[r*256 + 128 + j];
    } else {
        wa[j]       = bab[j];
        wa[j + 128] = bab[128 + j];
        wb[j] = 0.f; wb[j + 128] = 0.f;
    }
    __syncthreads();

    float accA, accB;
    if (r < 64) { accA = Wc1[r*128 + j]; accB = Wc1[(64 + r)*128 + j]; }
    else        { accA = bc1[j];         accB = 0.f; }

    const float* base = Wc1 + 128*128 + j;
    #pragma unroll 8
    for (int m = 0; m < 256; m++) {
        float wc = __ldg(&base[m*128]);
        accA += wa[m] * wc;
        accB += wb[m] * wc;
    }
    if (r < 64) { A[r*128 + j] = accA; B[r*128 + j] = accB; }
    else        { c[j] = accA; }
}

// ======== mlp2/edge: 512 threads, 16 warps x 16 rows = 256-row tiles ========
#define TRW2 256
#define T5T2 ((R5 + TRW2 - 1)/TRW2)
#define T6T2 ((R6 + TRW2 - 1)/TRW2)
#define TET2 ((NEDGE + TRW2 - 1)/TRW2)
#define NB5M 69

#define OFF_MW1T 0
#define OFF_MW2T 65536
#define OFF_MB1  98304
#define OFF_MB2  98816
#define OFF_MXH  99072
#define SMEM_MT  230144

// ---------------- mlp2 TENSOR ----------------
__global__ __launch_bounds__(512, 1)
void mlp2_kernel(const float* __restrict__ cyc5, const int* __restrict__ e2c5,
                 const float* __restrict__ cyc6, const int* __restrict__ e2c6,
                 const float* __restrict__ edge,
                 const float* __restrict__ W1, const float* __restrict__ b1,
                 const float* __restrict__ W2, const float* __restrict__ b2,
                 float* __restrict__ x5, float* __restrict__ x6)
{
    extern __shared__ char smc[];
    const int tid = threadIdx.x;
    u64* W1T = (u64*)(smc + OFF_MW1T);
    u64* W2T = (u64*)(smc + OFF_MW2T);
    float* B1S = (float*)(smc + OFF_MB1);
    float* B2S = (float*)(smc + OFF_MB2);
    for (int i = tid; i < 128*64; i += 512) {
        int n = i >> 6, p = i & 63;
        W1T[n*64 + (p ^ ((n&3)<<2))] = split4(W1[(2*p)*128 + n], W1[(2*p+1)*128 + n]);
    }
    for (int i = tid; i < 64*64; i += 512) {
        int n = i >> 6, p = i & 63;
        W2T[n*64 + (p ^ ((n&3)<<2))] = split4(W2[(2*p)*64 + n], W2[(2*p+1)*64 + n]);
    }
    if (tid < 128) B1S[tid] = b1[tid];
    else if (tid < 192) B2S[tid-128] = b2[tid-128];
    __syncthreads();

    const bool cl5 = blockIdx.x < NB5M;
    const float* cyc = cl5 ? cyc5 : cyc6;
    const int*   e2c = cl5 ? e2c5 : e2c6;
    float*      xout = cl5 ? x5  : x6;
    const int rows   = cl5 ? R5 : R6;
    const int ntiles = cl5 ? T5T2 : T6T2;
    const int b0     = cl5 ? blockIdx.x : blockIdx.x - NB5M;
    const int nb     = cl5 ? NB5M : (gridDim.x - NB5M);

    const int warp = tid >> 5, lane = tid & 31;
    const int g = lane >> 2, tg = lane & 3;
    const int sw = (g & 3) << 2;
    u64* XH = (u64*)(smc + OFF_MXH) + warp*1024;

    for (int tile = b0; tile < ntiles; tile += nb) {
        const int row0 = tile * TRW2;
        const int wrow0 = row0 + warp*16;
        const bool full = (row0 + TRW2 <= rows);

        #pragma unroll
        for (int r = 0; r < 16; r++) {
            int gr = wrow0 + r;
            int rs = (r & 3) << 2;
            float2 v0 = make_float2(0.f, 0.f);
            float2 v1 = make_float2(0.f, 0.f);
            if (full || gr < rows) {
                v0 = *(const float2*)&cyc[(size_t)gr*64 + lane*2];
                int2 e = *(const int2*)&e2c[gr*2];
                float2 a = *(const float2*)&edge[(size_t)e.x*64 + lane*2];
                float2 c2 = *(const float2*)&edge[(size_t)e.y*64 + lane*2];
                v1.x = a.x + c2.x; v1.y = a.y + c2.y;
            }
            XH[r*64 + (lane ^ rs)]        = split4(v0.x, v0.y);
            XH[r*64 + ((32 + lane) ^ rs)] = split4(v1.x, v1.y);
        }
        __syncwarp();

        const int ga = wrow0 + g, gb = wrow0 + g + 8;

        float d[16][4];
        #pragma unroll
        for (int j = 0; j < 16; j++) {
            float2 bb = *(const float2*)&B1S[j*8 + 2*tg];
            d[j][0] = bb.x; d[j][1] = bb.y; d[j][2] = bb.x; d[j][3] = bb.y;
        }
        for (int kk = 0; kk < 128; kk += 16) {
            int p0 = (kk >> 1) + tg;
            int c0 = p0 ^ sw, c1 = (p0 + 4) ^ sw;
            u64 t0 = XH[g*64     + c0];
            u64 t1 = XH[(g+8)*64 + c0];
            u64 t2 = XH[g*64     + c1];
            u64 t3 = XH[(g+8)*64 + c1];
            u32 ah0 = (u32)t0, al0 = (u32)(t0 >> 32);
            u32 ah1 = (u32)t1, al1 = (u32)(t1 >> 32);
            u32 ah2 = (u32)t2, al2 = (u32)(t2 >> 32);
            u32 ah3 = (u32)t3, al3 = (u32)(t3 >> 32);
            #pragma unroll
            for (int j = 0; j < 16; j++) {
                int n = j*8 + g;
                u64 w0 = W1T[n*64 + c0];
                u64 w1 = W1T[n*64 + c1];
                u32 bh0 = (u32)w0, bl0 = (u32)(w0 >> 32);
                u32 bh1 = (u32)w1, bl1 = (u32)(w1 >> 32);
                mma_bf16(d[j], ah0, ah1, ah2, ah3, bh0, bh1);
                mma_bf16(d[j], ah0, ah1, ah2, ah3, bl0, bl1);
                mma_bf16(d[j], al0, al1, al2, al3, bh0, bh1);
            }
        }
        __syncwarp();
        #pragma unroll
        for (int j = 0; j < 16; j++) {
            float v0 = fmaxf(d[j][0], 0.f), v1 = fmaxf(d[j][1], 0.f);
            float v2 = fmaxf(d[j][2], 0.f), v3 = fmaxf(d[j][3], 0.f);
            int hc = (j*4 + tg) ^ sw;
            XH[g*64     + hc] = split4(v0, v1);
            XH[(g+8)*64 + hc] = split4(v2, v3);
        }
        __syncwarp();

        float e[8][4];
        #pragma unroll
        for (int j = 0; j < 8; j++) {
            float2 bb = *(const float2*)&B2S[j*8 + 2*tg];
            e[j][0] = bb.x; e[j][1] = bb.y; e[j][2] = bb.x; e[j][3] = bb.y;
        }
        for (int kk = 0; kk < 128; kk += 16) {
            int p0 = (kk >> 1) + tg;
            int c0 = p0 ^ sw, c1 = (p0 + 4) ^ sw;
            u64 t0 = XH[g*64     + c0];
            u64 t1 = XH[(g+8)*64 + c0];
            u64 t2 = XH[g*64     + c1];
            u64 t3 = XH[(g+8)*64 + c1];
            u32 ah0 = (u32)t0, al0 = (u32)(t0 >> 32);
            u32 ah1 = (u32)t1, al1 = (u32)(t1 >> 32);
            u32 ah2 = (u32)t2, al2 = (u32)(t2 >> 32);
            u32 ah3 = (u32)t3, al3 = (u32)(t3 >> 32);
            #pragma unroll
            for (int j = 0; j < 8; j++) {
                int n = j*8 + g;
                u64 w0 = W2T[n*64 + c0];
                u64 w1 = W2T[n*64 + c1];
                u32 bh0 = (u32)w0, bl0 = (u32)(w0 >> 32);
                u32 bh1 = (u32)w1, bl1 = (u32)(w1 >> 32);
                mma_bf16(e[j], ah0, ah1, ah2, ah3, bh0, bh1);
                mma_bf16(e[j], ah0, ah1, ah2, ah3, bl0, bl1);
                mma_bf16(e[j], al0, al1, al2, al3, bh0, bh1);
            }
        }
        if (full) {
            #pragma unroll
            for (int j = 0; j < 8; j++) {
                *(float2*)&xout[(size_t)ga*64 + j*8 + 2*tg] =
                    make_float2(fmaxf(e[j][0], 0.f), fmaxf(e[j][1], 0.f));
                *(float2*)&xout[(size_t)gb*64 + j*8 + 2*tg] =
                    make_float2(fmaxf(e[j][2], 0.f), fmaxf(e[j][3], 0.f));
            }
        } else {
            #pragma unroll
            for (int j = 0; j < 8; j++) {
                if (ga < rows) *(float2*)&xout[(size_t)ga*64 + j*8 + 2*tg] =
                    make_float2(fmaxf(e[j][0], 0.f), fmaxf(e[j][1], 0.f));
                if (gb < rows) *(float2*)&xout[(size_t)gb*64 + j*8 + 2*tg] =
                    make_float2(fmaxf(e[j][2], 0.f), fmaxf(e[j][3], 0.f));
            }
        }
        __syncwarp();
    }
}

// ---------------- sB (merged, scalar — unchanged) ----------------
#define SMEM_SB ((64*128 + 128 + 128*64) * 4)
#define T5S ((NC5 + 127)/128)
#define T6S ((NC6 + 127)/128)
#define NB5S 76

__global__ __launch_bounds__(512, 1)
void sB_kernel(const float* __restrict__ x5, const float* __restrict__ x6,
               const float* __restrict__ B5, const float* __restrict__ c5,
               const float* __restrict__ B6, const float* __restrict__ c6,
               float* __restrict__ sB5, float* __restrict__ sB6)
{
    extern __shared__ float sm[];
    float* Bs = sm;
    float* cs = Bs + 64*128;
    float* ss = cs + 128;
    const int tid = threadIdx.x;

    const bool cl5 = blockIdx.x < NB5S;
    const float* xg = cl5 ? x5 : x6;
    const float* Bf = cl5 ? B5 : B6;
    const float* cf = cl5 ? c5 : c6;
    float*      sBg = cl5 ? sB5 : sB6;
    const int s      = cl5 ? SS5 : SS6;
    const int ncyc   = cl5 ? NC5 : NC6;
    const int ntiles = cl5 ? T5S : T6S;
    const int b0     = cl5 ? blockIdx.x : blockIdx.x - NB5S;
    const int nb     = cl5 ? NB5S : (gridDim.x - NB5S);

    for (int i = tid; i < 64*128; i += 512) Bs[i] = Bf[i];
    if (tid < 128) cs[tid] = cf[tid];
    __syncthreads();

    const int warp = tid >> 5, lane = tid & 31;
    float* wss = &ss[(warp*8)*64];

    for (int tile = b0; tile < ntiles; tile += nb) {
        const int cy0 = tile << 7;
        const int wcy0 = cy0 + warp*8;
        const bool full = (cy0 + 128 <= ncyc);
        if (full) {
            #pragma unroll
            for (int t = 0; t < 4; t++) {
                int i = t*32 + lane;
                int r = i >> 4, q = i & 15;
                int gc = wcy0 + r;
                float4 a = make_float4(0.f, 0.f, 0.f, 0.f);
                const float* xr = &xg[((size_t)gc * s) * 64 + q*4];
                for (int rr = 0; rr < s; rr++) {
                    float4 v = *(const float4*)&xr[(size_t)rr*64];
                    a.x += v.x; a.y += v.y; a.z += v.z; a.w += v.w;
                }
                *(float4*)&wss[r*64 + q*4] = a;
            }
        } else {
            #pragma unroll
            for (int t = 0; t < 4; t++) {
                int i = t*32 + lane;
                int r = i >> 4, q = i & 15;
                float4 a = make_float4(0.f, 0.f, 0.f, 0.f);
                int gc = wcy0 + r;
                if (gc < ncyc) {
                    const float* xr = &xg[((size_t)gc * s) * 64 + q*4];
                    for (int rr = 0; rr < s; rr++) {
                        float4 v = *(const float4*)&xr[(size_t)rr*64];
                        a.x += v.x; a.y += v.y; a.z += v.z; a.w += v.w;
                    }
                }
                *(float4*)&wss[r*64 + q*4] = a;
            }
        }
        __syncwarp();

        u64 acc[8][2];
        {
            ulonglong2 bb = *(const ulonglong2*)&cs[lane*4];
            #pragma unroll
            for (int r = 0; r < 8; r++) { acc[r][0] = bb.x; acc[r][1] = bb.y; }
        }
        #pragma unroll 2
        for (int k0 = 0; k0 < 64; k0 += 4) {
            ulonglong2 w0 = *(const ulonglong2*)&Bs[(k0+0)*128 + lane*4];
            ulonglong2 w1 = *(const ulonglong2*)&Bs[(k0+1)*128 + lane*4];
            ulonglong2 w2 = *(const ulonglong2*)&Bs[(k0+2)*128 + lane*4];
            ulonglong2 w3 = *(const ulonglong2*)&Bs[(k0+3)*128 + lane*4];
            #pragma unroll
            for (int r = 0; r < 8; r++) {
                float4 iv = *(const float4*)&wss[r*64 + k0];
                u64 p;
                p = pk(iv.x); fma2(acc[r][0], p, w0.x); fma2(acc[r][1], p, w0.y);
                p = pk(iv.y); fma2(acc[r][0], p, w1.x); fma2(acc[r][1], p, w1.y);
                p = pk(iv.z); fma2(acc[r][0], p, w2.x); fma2(acc[r][1], p, w2.y);
                p = pk(iv.w); fma2(acc[r][0], p, w3.x); fma2(acc[r][1], p, w3.y);
            }
        }
        #pragma unroll
        for (int r = 0; r < 8; r++) {
            int gc = wcy0 + r;
            if (full || gc < ncyc) {
                float2 a = up(acc[r][0]), b = up(acc[r][1]);
                float4 o; o.x = a.x; o.y = a.y; o.z = b.x; o.w = b.y;
                *(float4*)&sBg[(size_t)gc*128 + lane*4] = o;
            }
        }
        __syncwarp();
    }
}

// ---------------- cyc2 TENSOR: 384 thr, 12 warps (R14, unchanged) ----------------
#define TRW 192
#define T5T ((R5 + TRW - 1)/TRW)
#define T6T ((R6 + TRW - 1)/TRW)
#define OFF_AT   0
#define OFF_W2T  32768
#define OFF_W3T  98304
#define OFF_B2   131072
#define OFF_B3   131584
#define OFF_XH   131840
#define SMEM_CYC2T 230144
#define NB5C 69

__global__ __launch_bounds__(384, 1)
void cyc2_kernel(const float* __restrict__ x5, const float* __restrict__ sB5,
                 const float* __restrict__ A5,
                 const float* __restrict__ x6, const float* __restrict__ sB6,
                 const float* __restrict__ A6,
                 const float* __restrict__ Wc2, const float* __restrict__ bc2,
                 const float* __restrict__ Wc3, const float* __restrict__ bc3,
                 float* __restrict__ outbase)
{
    extern __shared__ char smc[];
    const int tid = threadIdx.x;

    const bool cl5 = blockIdx.x < NB5C;
    const float* xg  = cl5 ? x5 : x6;
    const float* sBg = cl5 ? sB5 : sB6;
    const float* Af  = cl5 ? A5 : A6;
    float* outp      = cl5 ? outbase : (outbase + (size_t)R5*64);
    const int rows   = cl5 ? R5 : R6;
    const int s      = cl5 ? SS5 : SS6;
    const int ntiles = cl5 ? T5T : T6T;
    const int b0c    = cl5 ? blockIdx.x : blockIdx.x - NB5C;
    const int nb     = cl5 ? NB5C : (gridDim.x - NB5C);

    u64* AT  = (u64*)(smc + OFF_AT);
    u64* W2T = (u64*)(smc + OFF_W2T);
    u64* W3T = (u64*)(smc + OFF_W3T);
    float* B2S = (float*)(smc + OFF_B2);
    float* B3S = (float*)(smc + OFF_B3);
    for (int i = tid; i < 128*32; i += 384) {
        int n = i >> 5, p = i & 31;
        AT[n*32 + (p ^ ((n&3)<<2))] = split4(Af[(2*p)*128 + n], Af[(2*p+1)*128 + n]);
    }
    for (int i = tid; i < 128*64; i += 384) {
        int n = i >> 6, p = i & 63;
        W2T[n*64 + (p ^ ((n&3)<<2))] = split4(Wc2[(2*p)*128 + n], Wc2[(2*p+1)*128 + n]);
    }
    for (int i = tid; i < 64*64; i += 384) {
        int n = i >> 6, p = i & 63;
        W3T[n*64 + (p ^ ((n&3)<<2))] = split4(Wc3[(2*p)*64 + n], Wc3[(2*p+1)*64 + n]);
    }
    if (tid < 128) B2S[tid] = bc2[tid];
    else if (tid < 192) B3S[tid-128] = bc3[tid-128];
    __syncthreads();

    const int warp = tid >> 5, lane = tid & 31;
    const int g = lane >> 2, tg = lane & 3;
    const int sw = (g & 3) << 2;
    u64* XH = (u64*)(smc + OFF_XH) + warp*1024;

    for (int tile = b0c; tile < ntiles; tile += nb) {
        const int row0 = tile * TRW;
        const int wrow0 = row0 + warp*16;
        const bool full = (row0 + TRW <= rows);

        #pragma unroll
        for (int r = 0; r < 16; r++) {
            int gr = wrow0 + r;
            float2 v = make_float2(0.f, 0.f);
            if (full || gr < rows) v = *(const float2*)&xg[(size_t)gr*64 + lane*2];
            XH[r*64 + 32 + (lane ^ ((r&3)<<2))] = split4(v.x, v.y);
        }
        __syncwarp();

        const int ga = wrow0 + g, gb = wrow0 + g + 8;
        const int ca = ((full || ga < rows) ? ga : 0) / s;
        const int cb = ((full || gb < rows) ? gb : 0) / s;
        const float* pA = sBg + (size_t)ca*128;
        const float* pB = sBg + (size_t)cb*128;

        float d[16][4];
        #pragma unroll
        for (int j = 0; j < 16; j++) {
            float2 va = *(const float2*)&pA[j*8 + 2*tg];
            float2 vb = *(const float2*)&pB[j*8 + 2*tg];
            d[j][0] = va.x; d[j][1] = va.y; d[j][2] = vb.x; d[j][3] = vb.y;
        }
        for (int kk = 0; kk < 64; kk += 16) {
            int p0 = (kk >> 1) + tg;
            int c0 = 32 + (p0 ^ sw), c1 = 32 + ((p0 + 4) ^ sw);
            u64 t0 = XH[g*64     + c0];
            u64 t1 = XH[(g+8)*64 + c0];
            u64 t2 = XH[g*64     + c1];
            u64 t3 = XH[(g+8)*64 + c1];
            u32 ah0 = (u32)t0, al0 = (u32)(t0 >> 32);
            u32 ah1 = (u32)t1, al1 = (u32)(t1 >> 32);
            u32 ah2 = (u32)t2, al2 = (u32)(t2 >> 32);
            u32 ah3 = (u32)t3, al3 = (u32)(t3 >> 32);
            int w0i = p0 ^ sw, w1i = (p0 + 4) ^ sw;
            #pragma unroll
            for (int j = 0; j < 16; j++) {
                int n = j*8 + g;
                u64 w0 = AT[n*32 + w0i];
                u64 w1 = AT[n*32 + w1i];
                u32 bh0 = (u32)w0, bl0 = (u32)(w0 >> 32);
                u32 bh1 = (u32)w1, bl1 = (u32)(w1 >> 32);
                mma_bf16(d[j], ah0, ah1, ah2, ah3, bh0, bh1);
                mma_bf16(d[j], ah0, ah1, ah2, ah3, bl0, bl1);
                mma_bf16(d[j], al0, al1, al2, al3, bh0, bh1);
            }
        }
        __syncwarp();
        #pragma unroll
        for (int j = 0; j < 16; j++) {
            float v0 = fmaxf(d[j][0], 0.f), v1 = fmaxf(d[j][1], 0.f);
            float v2 = fmaxf(d[j][2], 0.f), v3 = fmaxf(d[j][3], 0.f);
            int hc = (j*4 + tg) ^ sw;
            XH[g*64     + hc] = split4(v0, v1);
            XH[(g+8)*64 + hc] = split4(v2, v3);
        }
        __syncwarp();

        #pragma unroll
        for (int j = 0; j < 16; j++) {
            float2 bb = *(const float2*)&B2S[j*8 + 2*tg];
            d[j][0] = bb.x; d[j][1] = bb.y; d[j][2] = bb.x; d[j][3] = bb.y;
        }
        for (int kk = 0; kk < 128; kk += 16) {
            int p0 = (kk >> 1) + tg;
            int c0 = p0 ^ sw, c1 = (p0 + 4) ^ sw;
            u64 t0 = XH[g*64     + c0];
            u64 t1 = XH[(g+8)*64 + c0];
            u64 t2 = XH[g*64     + c1];
            u64 t3 = XH[(g+8)*64 + c1];
            u32 ah0 = (u32)t0, al0 = (u32)(t0 >> 32);
            u32 ah1 = (u32)t1, al1 = (u32)(t1 >> 32);
            u32 ah2 = (u32)t2, al2 = (u32)(t2 >> 32);
            u32 ah3 = (u32)t3, al3 = (u32)(t3 >> 32);
            #pragma unroll
            for (int j = 0; j < 16; j++) {
                int n = j*8 + g;
                u64 w0 = W2T[n*64 + c0];
                u64 w1 = W2T[n*64 + c1];
                u32 bh0 = (u32)w0, bl0 = (u32)(w0 >> 32);
                u32 bh1 = (u32)w1, bl1 = (u32)(w1 >> 32);
                mma_bf16(d[j], ah0, ah1, ah2, ah3, bh0, bh1);
                mma_bf16(d[j], ah0, ah1, ah2, ah3, bl0, bl1);
                mma_bf16(d[j], al0, al1, al2, al3, bh0, bh1);
            }
        }
        __syncwarp();
        #pragma unroll
        for (int j = 0; j < 16; j++) {
            float v0 = fmaxf(d[j][0], 0.f), v1 = fmaxf(d[j][1], 0.f);
            float v2 = fmaxf(d[j][2], 0.f), v3 = fmaxf(d[j][3], 0.f);
            int hc = (j*4 + tg) ^ sw;
            XH[g*64     + hc] = split4(v0, v1);
            XH[(g+8)*64 + hc] = split4(v2, v3);
        }
        __syncwarp();

        float e[8][4];
        #pragma unroll
        for (int j = 0; j < 8; j++) {
            float2 bb = *(const float2*)&B3S[j*8 + 2*tg];
            e[j][0] = bb.x; e[j][1] = bb.y; e[j][2] = bb.x; e[j][3] = bb.y;
        }
        for (int kk = 0; kk < 128; kk += 16) {
            int p0 = (kk >> 1) + tg;
            int c0 = p0 ^ sw, c1 = (p0 + 4) ^ sw;
            u64 t0 = XH[g*64     + c0];
            u64 t1 = XH[(g+8)*64 + c0];
            u64 t2 = XH[g*64     + c1];
            u64 t3 = XH[(g+8)*64 + c1];
            u32 ah0 = (u32)t0, al0 = (u32)(t0 >> 32);
            u32 ah1 = (u32)t1, al1 = (u32)(t1 >> 32);
            u32 ah2 = (u32)t2, al2 = (u32)(t2 >> 32);
            u32 ah3 = (u32)t3, al3 = (u32)(t3 >> 32);
            #pragma unroll
            for (int j = 0; j < 8; j++) {
                int n = j*8 + g;
                u64 w0 = W3T[n*64 + c0];
                u64 w1 = W3T[n*64 + c1];
                u32 bh0 = (u32)w0, bl0 = (u32)(w0 >> 32);
                u32 bh1 = (u32)w1, bl1 = (u32)(w1 >> 32);
                mma_bf16(e[j], ah0, ah1, ah2, ah3, bh0, bh1);
                mma_bf16(e[j], ah0, ah1, ah2, ah3, bl0, bl1);
                mma_bf16(e[j], al0, al1, al2, al3, bh0, bh1);
            }
        }
        if (full) {
            #pragma unroll
            for (int j = 0; j < 8; j++) {
                *(float2*)&outp[(size_t)ga*64 + j*8 + 2*tg] = make_float2(e[j][0], e[j][1]);
                *(float2*)&outp[(size_t)gb*64 + j*8 + 2*tg] = make_float2(e[j][2], e[j][3]);
            }
        } else {
            #pragma unroll
            for (int j = 0; j < 8; j++) {
                if (ga < rows) *(float2*)&outp[(size_t)ga*64 + j*8 + 2*tg] = make_float2(e[j][0], e[j][1]);
                if (gb < rows) *(float2*)&outp[(size_t)gb*64 + j*8 + 2*tg] = make_float2(e[j][2], e[j][3]);
            }
        }
        __syncwarp();
    }
}

// ---------------- edge TENSOR: 512 thr, 16 warps ----------------
__global__ __launch_bounds__(512, 1)
void edge_kernel(const float* __restrict__ edge, const int* __restrict__ c2e,
                 const float* __restrict__ cycout,
                 const float* __restrict__ We1, const float* __restrict__ be1,
                 const float* __restrict__ We2, const float* __restrict__ be2,
                 float* __restrict__ outp)
{
    extern __shared__ char smc[];
    const int tid = threadIdx.x;
    u64* W1T = (u64*)(smc + OFF_MW1T);
    u64* W2T = (u64*)(smc + OFF_MW2T);
    float* B1S = (float*)(smc + OFF_MB1);
    float* B2S = (float*)(smc + OFF_MB2);
    for (int i = tid; i < 128*64; i += 512) {
        int n = i >> 6, p = i & 63;
        W1T[n*64 + (p ^ ((n&3)<<2))] = split4(We1[(2*p)*128 + n], We1[(2*p+1)*128 + n]);
    }
    for (int i = tid; i < 64*64; i += 512) {
        int n = i >> 6, p = i & 63;
        W2T[n*64 + (p ^ ((n&3)<<2))] = split4(We2[(2*p)*64 + n], We2[(2*p+1)*64 + n]);
    }
    if (tid < 128) B1S[tid] = be1[tid];
    else if (tid < 192) B2S[tid-128] = be2[tid-128];
    __syncthreads();

    const int warp = tid >> 5, lane = tid & 31;
    const int g = lane >> 2, tg = lane & 3;
    const int sw = (g & 3) << 2;
    u64* XH = (u64*)(smc + OFF_MXH) + warp*1024;
    const int rows = NEDGE;

    for (int tile = blockIdx.x; tile < TET2; tile += gridDim.x) {
        const int row0 = tile * TRW2;
        const int wrow0 = row0 + warp*16;
        const bool full = (row0 + TRW2 <= rows);

        #pragma unroll
        for (int r = 0; r < 16; r++) {
            int gr = wrow0 + r;
            int rs = (r & 3) << 2;
            float2 v0 = make_float2(0.f, 0.f);
            float2 v1 = make_float2(0.f, 0.f);
            if (full || gr < rows) {
                v0 = *(const float2*)&edge[(size_t)gr*64 + lane*2];
                int4 ix = *(const int4*)&c2e[gr*4];
                float2 a = *(const float2*)&cycout[(size_t)ix.x*64 + lane*2];
                float2 b = *(const float2*)&cycout[(size_t)ix.y*64 + lane*2];
                float2 c = *(const float2*)&cycout[(size_t)ix.z*64 + lane*2];
                float2 dd = *(const float2*)&cycout[(size_t)ix.w*64 + lane*2];
                v1.x = a.x + b.x + c.x + dd.x;
                v1.y = a.y + b.y + c.y + dd.y;
            }
            XH[r*64 + (lane ^ rs)]        = split4(v0.x, v0.y);
            XH[r*64 + ((32 + lane) ^ rs)] = split4(v1.x, v1.y);
        }
        __syncwarp();

        const int ga = wrow0 + g, gb = wrow0 + g + 8;

        float d[16][4];
        #pragma unroll
        for (int j = 0; j < 16; j++) {
            float2 bb = *(const float2*)&B1S[j*8 + 2*tg];
            d[j][0] = bb.x; d[j][1] = bb.y; d[j][2] = bb.x; d[j][3] = bb.y;
        }
        for (int kk = 0; kk < 128; kk += 16) {
            int p0 = (kk >> 1) + tg;
            int c0 = p0 ^ sw, c1 = (p0 + 4) ^ sw;
            u64 t0 = XH[g*64     + c0];
            u64 t1 = XH[(g+8)*64 + c0];
            u64 t2 = XH[g*64     + c1];
            u64 t3 = XH[(g+8)*64 + c1];
            u32 ah0 = (u32)t0, al0 = (u32)(t0 >> 32);
            u32 ah1 = (u32)t1, al1 = (u32)(t1 >> 32);
            u32 ah2 = (u32)t2, al2 = (u32)(t2 >> 32);
            u32 ah3 = (u32)t3, al3 = (u32)(t3 >> 32);
            #pragma unroll
            for (int j = 0; j < 16; j++) {
                int n = j*8 + g;
                u64 w0 = W1T[n*64 + c0];
                u64 w1 = W1T[n*64 + c1];
                u32 bh0 = (u32)w0, bl0 = (u32)(w0 >> 32);
                u32 bh1 = (u32)w1, bl1 = (u32)(w1 >> 32);
                mma_bf16(d[j], ah0, ah1, ah2, ah3, bh0, bh1);
                mma_bf16(d[j], ah0, ah1, ah2, ah3, bl0, bl1);
                mma_bf16(d[j], al0, al1, al2, al3, bh0, bh1);
            }
        }
        __syncwarp();
        #pragma unroll
        for (int j = 0; j < 16; j++) {
            float v0 = fmaxf(d[j][0], 0.f), v1 = fmaxf(d[j][1], 0.f);
            float v2 = fmaxf(d[j][2], 0.f), v3 = fmaxf(d[j][3], 0.f);
            int hc = (j*4 + tg) ^ sw;
            XH[g*64     + hc] = split4(v0, v1);
            XH[(g+8)*64 + hc] = split4(v2, v3);
        }
        __syncwarp();

        float e[8][4];
        #pragma unroll
        for (int j = 0; j < 8; j++) {
            float2 bb = *(const float2*)&B2S[j*8 + 2*tg];
            e[j][0] = bb.x; e[j][1] = bb.y; e[j][2] = bb.x; e[j][3] = bb.y;
        }
        for (int kk = 0; kk < 128; kk += 16) {
            int p0 = (kk >> 1) + tg;
            int c0 = p0 ^ sw, c1 = (p0 + 4) ^ sw;
            u64 t0 = XH[g*64     + c0];
            u64 t1 = XH[(g+8)*64 + c0];
            u64 t2 = XH[g*64     + c1];
            u64 t3 = XH[(g+8)*64 + c1];
            u32 ah0 = (u32)t0, al0 = (u32)(t0 >> 32);
            u32 ah1 = (u32)t1, al1 = (u32)(t1 >> 32);
            u32 ah2 = (u32)t2, al2 = (u32)(t2 >> 32);
            u32 ah3 = (u32)t3, al3 = (u32)(t3 >> 32);
            #pragma unroll
            for (int j = 0; j < 8; j++) {
                int n = j*8 + g;
                u64 w0 = W2T[n*64 + c0];
                u64 w1 = W2T[n*64 + c1];
                u32 bh0 = (u32)w0, bl0 = (u32)(w0 >> 32);
                u32 bh1 = (u32)w1, bl1 = (u32)(w1 >> 32);
                mma_bf16(e[j], ah0, ah1, ah2, ah3, bh0, bh1);
                mma_bf16(e[j], ah0, ah1, ah2, ah3, bl0, bl1);
                mma_bf16(e[j], al0, al1, al2, al3, bh0, bh1);
            }
        }
        if (full) {
            #pragma unroll
            for (int j = 0; j < 8; j++) {
                *(float2*)&outp[(size_t)ga*64 + j*8 + 2*tg] = make_float2(e[j][0], e[j][1]);
                *(float2*)&outp[(size_t)gb*64 + j*8 + 2*tg] = make_float2(e[j][2], e[j][3]);
            }
        } else {
            #pragma unroll
            for (int j = 0; j < 8; j++) {
                if (ga < rows) *(float2*)&outp[(size_t)ga*64 + j*8 + 2*tg] = make_float2(e[j][0], e[j][1]);
                if (gb < rows) *(float2*)&outp[(size_t)gb*64 + j*8 + 2*tg] = make_float2(e[j][2], e[j][3]);
            }
        }
        __syncwarp();
    }
}

// ---------------- launch ----------------
extern "C" void kernel_launch(void* const* d_in, const int* in_sizes, int n_in,
                              void* d_out, int out_size)
{
    const float* edge_rep = (const float*)d_in[0];
    const float* cyc5 = (const float*)d_in[1];
    const float* cyc6 = (const float*)d_in[2];
    const int*   e2c5 = (const int*)d_in[3];
    const int*   e2c6 = (const int*)d_in[4];
    const int*   c2e  = (const int*)d_in[5];
    const float* W1  = (const float*)d_in[6];
    const float* b1  = (const float*)d_in[7];
    const float* W2  = (const float*)d_in[8];
    const float* b2  = (const float*)d_in[9];
    const float* Wc1 = (const float*)d_in[10];
    const float* bc1 = (const float*)d_in[11];
    const float* Wc2 = (const float*)d_in[12];
    const float* bc2 = (const float*)d_in[13];
    const float* Wc3 = (const float*)d_in[14];
    const float* bc3 = (const float*)d_in[15];
    const float* We1 = (const float*)d_in[16];
    const float* be1 = (const float*)d_in[17];
    const float* We2 = (const float*)d_in[18];
    const float* be2 = (const float*)d_in[19];
    const float* Wid5  = (const float*)d_in[20];
    const float* Wsum5 = (const float*)d_in[21];
    const float* bab5  = (const float*)d_in[22];
    const float* Wid6  = (const float*)d_in[23];
    const float* Wsum6 = (const float*)d_in[24];
    const float* bab6  = (const float*)d_in[25];
    float* out = (float*)d_out;

    float *x5, *x6, *sB5, *sB6, *A5, *B5, *c5, *A6, *B6, *c6;
    cudaGetSymbolAddress((void**)&x5,  g_x5);
    cudaGetSymbolAddress((void**)&x6,  g_x6);
    cudaGetSymbolAddress((void**)&sB5, g_sB5);
    cudaGetSymbolAddress((void**)&sB6, g_sB6);
    cudaGetSymbolAddress((void**)&A5,  g_A5);
    cudaGetSymbolAddress((void**)&B5,  g_B5);
    cudaGetSymbolAddress((void**)&c5,  g_c5);
    cudaGetSymbolAddress((void**)&A6,  g_A6);
    cudaGetSymbolAddress((void**)&B6,  g_B6);
    cudaGetSymbolAddress((void**)&c6,  g_c6);

    cudaFuncSetAttribute(mlp2_kernel, cudaFuncAttributeMaxDynamicSharedMemorySize, SMEM_MT);
    cudaFuncSetAttribute(edge_kernel, cudaFuncAttributeMaxDynamicSharedMemorySize, SMEM_MT);
    cudaFuncSetAttribute(cyc2_kernel, cudaFuncAttributeMaxDynamicSharedMemorySize, SMEM_CYC2T);
    cudaFuncSetAttribute(sB_kernel,   cudaFuncAttributeMaxDynamicSharedMemorySize, SMEM_SB);

    const int NBLK = 152;

    fold_all_kernel<<<130, 128>>>(Wc1, bc1, Wid5, Wsum5, bab5, Wid6, Wsum6, bab6,
                                  A5, B5, c5, A6, B6, c6);

    mlp2_kernel<<<NBLK, 512, SMEM_MT>>>(cyc5, e2c5, cyc6, e2c6, edge_rep,
                                        W1, b1, W2, b2, x5, x6);

    sB_kernel<<<NBLK, 512, SMEM_SB>>>(x5, x6, B5, c5, B6, c6, sB5, sB6);

    cyc2_kernel<<<NBLK, 384, SMEM_CYC2T>>>(x5, sB5, A5, x6, sB6, A6,
                                           Wc2, bc2, Wc3, bc3,
                                           out + (size_t)NEDGE*64);

    edge_kernel<<<NBLK, 512, SMEM_MT>>>(edge_rep, c2e, out + (size_t)NEDGE*64,
                                        We1, be1, We2, be2, out);
}

// round 16
// speedup vs baseline: 1.4195x; 1.4195x over previous
#include <cuda_runtime.h>
#include <cuda_bf16.h>

#define DD 64
#define NEDGE 200000
#define NC5 30000
#define SS5 5
#define NC6 30000
#define SS6 6
#define R5 (NC5*SS5)
#define R6 (NC6*SS6)

typedef unsigned long long u64;
typedef unsigned int u32;

// ---------------- packed f32x2 helpers (Blackwell) ----------------
__device__ __forceinline__ u64 pk(float v) {
    u64 r; asm("mov.b64 %0, {%1, %1};" : "=l"(r) : "f"(v)); return r;
}
__device__ __forceinline__ void fma2(u64& d, u64 a, u64 b) {
    asm("fma.rn.f32x2 %0, %1, %2, %0;" : "+l"(d) : "l"(a), "l"(b));
}
__device__ __forceinline__ float2 up(u64 v) {
    float2 r; asm("mov.b64 {%0, %1}, %2;" : "=f"(r.x), "=f"(r.y) : "l"(v)); return r;
}

// ---------------- bf16 split helpers ----------------
__device__ __forceinline__ u64 split4(float x, float y) {
    __nv_bfloat16 bx = __float2bfloat16_rn(x), by = __float2bfloat16_rn(y);
    float fx = __bfloat162float(bx), fy = __bfloat162float(by);
    __nv_bfloat16 cx = __float2bfloat16_rn(x - fx), cy = __float2bfloat16_rn(y - fy);
    u32 hi = ((u32)(*(unsigned short*)&by) << 16) | *(unsigned short*)&bx;
    u32 lo = ((u32)(*(unsigned short*)&cy) << 16) | *(unsigned short*)&cx;
    return ((u64)lo << 32) | hi;
}
__device__ __forceinline__ void mma_bf16(float d[4], u32 a0, u32 a1, u32 a2, u32 a3,
                                         u32 b0, u32 b1) {
    asm volatile(
        "mma.sync.aligned.m16n8k16.row.col.f32.bf16.bf16.f32 "
        "{%0,%1,%2,%3},{%4,%5,%6,%7},{%8,%9},{%0,%1,%2,%3};"
        : "+f"(d[0]), "+f"(d[1]), "+f"(d[2]), "+f"(d[3])
        : "r"(a0), "r"(a1), "r"(a2), "r"(a3), "r"(b0), "r"(b1));
}

// ---------------- scratch ----------------
__device__ float g_x5[R5*DD];
__device__ float g_x6[R6*DD];
__device__ float g_sB5[NC5*128];
__device__ float g_sB6[NC6*128];
__device__ float g_A5[64*128];
__device__ float g_B5[64*128];
__device__ float g_c5[128];
__device__ float g_A6[64*128];
__device__ float g_B6[64*128];
__device__ float g_c6[128];

// ---------------- weight folding ----------------
__global__ __launch_bounds__(128)
void fold_all_kernel(const float* __restrict__ Wc1, const float* __restrict__ bc1,
                     const float* __restrict__ Wid5, const float* __restrict__ Wsum5,
                     const float* __restrict__ bab5,
                     const float* __restrict__ Wid6, const float* __restrict__ Wsum6,
                     const float* __restrict__ bab6,
                     float* __restrict__ A5, float* __restrict__ B5, float* __restrict__ c5,
                     float* __restrict__ A6, float* __restrict__ B6, float* __restrict__ c6)
{
    int b = blockIdx.x;
    int sz = b / 65;
    int r  = b % 65;
    const float* Wid  = sz ? Wid6  : Wid5;
    const float* Wsum = sz ? Wsum6 : Wsum5;
    const float* bab  = sz ? bab6  : bab5;
    float* A = sz ? A6 : A5;
    float* B = sz ? B6 : B5;
    float* c = sz ? c6 : c5;

    __shared__ float wa[256], wb[256];
    int j = threadIdx.x;
    if (r < 64) {
        wa[j]       = Wid[r*256 + j];
        wa[j + 128] = Wid[r*256 + 128 + j];
        wb[j]       = Wsum[r*256 + j];
        wb[j + 128] = Wsum[r*256 + 128 + j];
    } else {
        wa[j]       = bab[j];
        wa[j + 128] = bab[128 + j];
        wb[j] = 0.f; wb[j + 128] = 0.f;
    }
    __syncthreads();

    float accA, accB;
    if (r < 64) { accA = Wc1[r*128 + j]; accB = Wc1[(64 + r)*128 + j]; }
    else        { accA = bc1[j];         accB = 0.f; }

    const float* base = Wc1 + 128*128 + j;
    #pragma unroll 8
    for (int m = 0; m < 256; m++) {
        float wc = __ldg(&base[m*128]);
        accA += wa[m] * wc;
        accB += wb[m] * wc;
    }
    if (r < 64) { A[r*128 + j] = accA; B[r*128 + j] = accB; }
    else        { c[j] = accA; }
}

// ======== tensor kernels: 384 threads, 12 warps x 16 rows = 192-row tiles ========
#define TRW 192
#define T5T ((R5 + TRW - 1)/TRW)
#define T6T ((R6 + TRW - 1)/TRW)
#define TET ((NEDGE + TRW - 1)/TRW)
#define NB5M 69

// -------- mlp2/edge smem: W1T 65536, W2T 32768, b 768, XH 12*8192 --------
#define OFF_MW1T 0
#define OFF_MW2T 65536
#define OFF_MB1  98304
#define OFF_MB2  98816
#define OFF_MXH  99072
#define SMEM_MT  197376

// ---------------- mlp2 TENSOR: x = relu(relu([cyc|e-gather]@W1+b1)@W2+b2) ----------------
__global__ __launch_bounds__(384, 1)
void mlp2_kernel(const float* __restrict__ cyc5, const int* __restrict__ e2c5,
                 const float* __restrict__ cyc6, const int* __restrict__ e2c6,
                 const float* __restrict__ edge,
                 const float* __restrict__ W1, const float* __restrict__ b1,
                 const float* __restrict__ W2, const float* __restrict__ b2,
                 float* __restrict__ x5, float* __restrict__ x6)
{
    extern __shared__ char smc[];
    const int tid = threadIdx.x;
    u64* W1T = (u64*)(smc + OFF_MW1T);
    u64* W2T = (u64*)(smc + OFF_MW2T);
    float* B1S = (float*)(smc + OFF_MB1);
    float* B2S = (float*)(smc + OFF_MB2);
    for (int i = tid; i < 128*64; i += 384) {
        int n = i >> 6, p = i & 63;
        W1T[n*64 + (p ^ ((n&3)<<2))] = split4(W1[(2*p)*128 + n], W1[(2*p+1)*128 + n]);
    }
    for (int i = tid; i < 64*64; i += 384) {
        int n = i >> 6, p = i & 63;
        W2T[n*64 + (p ^ ((n&3)<<2))] = split4(W2[(2*p)*64 + n], W2[(2*p+1)*64 + n]);
    }
    if (tid < 128) B1S[tid] = b1[tid];
    else if (tid < 192) B2S[tid-128] = b2[tid-128];
    __syncthreads();

    const bool cl5 = blockIdx.x < NB5M;
    const float* cyc = cl5 ? cyc5 : cyc6;
    const int*   e2c = cl5 ? e2c5 : e2c6;
    float*      xout = cl5 ? x5  : x6;
    const int rows   = cl5 ? R5 : R6;
    const int ntiles = cl5 ? T5T : T6T;
    const int b0     = cl5 ? blockIdx.x : blockIdx.x - NB5M;
    const int nb     = cl5 ? NB5M : (gridDim.x - NB5M);

    const int warp = tid >> 5, lane = tid & 31;
    const int g = lane >> 2, tg = lane & 3;
    const int sw = (g & 3) << 2;
    u64* XH = (u64*)(smc + OFF_MXH) + warp*1024;   // [16][64], X then H (aliased)

    for (int tile = b0; tile < ntiles; tile += nb) {
        const int row0 = tile * TRW;
        const int wrow0 = row0 + warp*16;
        const bool full = (row0 + TRW <= rows);

        #pragma unroll
        for (int r = 0; r < 16; r++) {
            int gr = wrow0 + r;
            int rs = (r & 3) << 2;
            float2 v0 = make_float2(0.f, 0.f);
            float2 v1 = make_float2(0.f, 0.f);
            if (full || gr < rows) {
                v0 = *(const float2*)&cyc[(size_t)gr*64 + lane*2];
                int2 e = *(const int2*)&e2c[gr*2];
                float2 a = *(const float2*)&edge[(size_t)e.x*64 + lane*2];
                float2 c2 = *(const float2*)&edge[(size_t)e.y*64 + lane*2];
                v1.x = a.x + c2.x; v1.y = a.y + c2.y;
            }
            XH[r*64 + (lane ^ rs)]        = split4(v0.x, v0.y);
            XH[r*64 + ((32 + lane) ^ rs)] = split4(v1.x, v1.y);
        }
        __syncwarp();

        const int ga = wrow0 + g, gb = wrow0 + g + 8;

        float d[16][4];
        #pragma unroll
        for (int j = 0; j < 16; j++) {
            float2 bb = *(const float2*)&B1S[j*8 + 2*tg];
            d[j][0] = bb.x; d[j][1] = bb.y; d[j][2] = bb.x; d[j][3] = bb.y;
        }
        for (int kk = 0; kk < 128; kk += 16) {
            int p0 = (kk >> 1) + tg;
            int c0 = p0 ^ sw, c1 = (p0 + 4) ^ sw;
            u64 t0 = XH[g*64     + c0];
            u64 t1 = XH[(g+8)*64 + c0];
            u64 t2 = XH[g*64     + c1];
            u64 t3 = XH[(g+8)*64 + c1];
            u32 ah0 = (u32)t0, al0 = (u32)(t0 >> 32);
            u32 ah1 = (u32)t1, al1 = (u32)(t1 >> 32);
            u32 ah2 = (u32)t2, al2 = (u32)(t2 >> 32);
            u32 ah3 = (u32)t3, al3 = (u32)(t3 >> 32);
            #pragma unroll
            for (int j = 0; j < 16; j++) {
                int n = j*8 + g;
                u64 w0 = W1T[n*64 + c0];
                u64 w1 = W1T[n*64 + c1];
                u32 bh0 = (u32)w0, bl0 = (u32)(w0 >> 32);
                u32 bh1 = (u32)w1, bl1 = (u32)(w1 >> 32);
                mma_bf16(d[j], ah0, ah1, ah2, ah3, bh0, bh1);
                mma_bf16(d[j], ah0, ah1, ah2, ah3, bl0, bl1);
                mma_bf16(d[j], al0, al1, al2, al3, bh0, bh1);
            }
        }
        __syncwarp();
        #pragma unroll
        for (int j = 0; j < 16; j++) {
            float v0 = fmaxf(d[j][0], 0.f), v1 = fmaxf(d[j][1], 0.f);
            float v2 = fmaxf(d[j][2], 0.f), v3 = fmaxf(d[j][3], 0.f);
            int hc = (j*4 + tg) ^ sw;
            XH[g*64     + hc] = split4(v0, v1);
            XH[(g+8)*64 + hc] = split4(v2, v3);
        }
        __syncwarp();

        float e[8][4];
        #pragma unroll
        for (int j = 0; j < 8; j++) {
            float2 bb = *(const float2*)&B2S[j*8 + 2*tg];
            e[j][0] = bb.x; e[j][1] = bb.y; e[j][2] = bb.x; e[j][3] = bb.y;
        }
        for (int kk = 0; kk < 128; kk += 16) {
            int p0 = (kk >> 1) + tg;
            int c0 = p0 ^ sw, c1 = (p0 + 4) ^ sw;
            u64 t0 = XH[g*64     + c0];
            u64 t1 = XH[(g+8)*64 + c0];
            u64 t2 = XH[g*64     + c1];
            u64 t3 = XH[(g+8)*64 + c1];
            u32 ah0 = (u32)t0, al0 = (u32)(t0 >> 32);
            u32 ah1 = (u32)t1, al1 = (u32)(t1 >> 32);
            u32 ah2 = (u32)t2, al2 = (u32)(t2 >> 32);
            u32 ah3 = (u32)t3, al3 = (u32)(t3 >> 32);
            #pragma unroll
            for (int j = 0; j < 8; j++) {
                int n = j*8 + g;
                u64 w0 = W2T[n*64 + c0];
                u64 w1 = W2T[n*64 + c1];
                u32 bh0 = (u32)w0, bl0 = (u32)(w0 >> 32);
                u32 bh1 = (u32)w1, bl1 = (u32)(w1 >> 32);
                mma_bf16(e[j], ah0, ah1, ah2, ah3, bh0, bh1);
                mma_bf16(e[j], ah0, ah1, ah2, ah3, bl0, bl1);
                mma_bf16(e[j], al0, al1, al2, al3, bh0, bh1);
            }
        }
        if (full) {
            #pragma unroll
            for (int j = 0; j < 8; j++) {
                *(float2*)&xout[(size_t)ga*64 + j*8 + 2*tg] =
                    make_float2(fmaxf(e[j][0], 0.f), fmaxf(e[j][1], 0.f));
                *(float2*)&xout[(size_t)gb*64 + j*8 + 2*tg] =
                    make_float2(fmaxf(e[j][2], 0.f), fmaxf(e[j][3], 0.f));
            }
        } else {
            #pragma unroll
            for (int j = 0; j < 8; j++) {
                if (ga < rows) *(float2*)&xout[(size_t)ga*64 + j*8 + 2*tg] =
                    make_float2(fmaxf(e[j][0], 0.f), fmaxf(e[j][1], 0.f));
                if (gb < rows) *(float2*)&xout[(size_t)gb*64 + j*8 + 2*tg] =
                    make_float2(fmaxf(e[j][2], 0.f), fmaxf(e[j][3], 0.f));
            }
        }
        __syncwarp();
    }
}

// ---------------- sB (merged, scalar — unchanged) ----------------
#define SMEM_SB ((64*128 + 128 + 128*64) * 4)
#define T5S ((NC5 + 127)/128)
#define T6S ((NC6 + 127)/128)
#define NB5S 76

__global__ __launch_bounds__(512, 1)
void sB_kernel(const float* __restrict__ x5, const float* __restrict__ x6,
               const float* __restrict__ B5, const float* __restrict__ c5,
               const float* __restrict__ B6, const float* __restrict__ c6,
               float* __restrict__ sB5, float* __restrict__ sB6)
{
    extern __shared__ float sm[];
    float* Bs = sm;
    float* cs = Bs + 64*128;
    float* ss = cs + 128;
    const int tid = threadIdx.x;

    const bool cl5 = blockIdx.x < NB5S;
    const float* xg = cl5 ? x5 : x6;
    const float* Bf = cl5 ? B5 : B6;
    const float* cf = cl5 ? c5 : c6;
    float*      sBg = cl5 ? sB5 : sB6;
    const int s      = cl5 ? SS5 : SS6;
    const int ncyc   = cl5 ? NC5 : NC6;
    const int ntiles = cl5 ? T5S : T6S;
    const int b0     = cl5 ? blockIdx.x : blockIdx.x - NB5S;
    const int nb     = cl5 ? NB5S : (gridDim.x - NB5S);

    for (int i = tid; i < 64*128; i += 512) Bs[i] = Bf[i];
    if (tid < 128) cs[tid] = cf[tid];
    __syncthreads();

    const int warp = tid >> 5, lane = tid & 31;
    float* wss = &ss[(warp*8)*64];

    for (int tile = b0; tile < ntiles; tile += nb) {
        const int cy0 = tile << 7;
        const int wcy0 = cy0 + warp*8;
        const bool full = (cy0 + 128 <= ncyc);
        if (full) {
            #pragma unroll
            for (int t = 0; t < 4; t++) {
                int i = t*32 + lane;
                int r = i >> 4, q = i & 15;
                int gc = wcy0 + r;
                float4 a = make_float4(0.f, 0.f, 0.f, 0.f);
                const float* xr = &xg[((size_t)gc * s) * 64 + q*4];
                for (int rr = 0; rr < s; rr++) {
                    float4 v = *(const float4*)&xr[(size_t)rr*64];
                    a.x += v.x; a.y += v.y; a.z += v.z; a.w += v.w;
                }
                *(float4*)&wss[r*64 + q*4] = a;
            }
        } else {
            #pragma unroll
            for (int t = 0; t < 4; t++) {
                int i = t*32 + lane;
                int r = i >> 4, q = i & 15;
                float4 a = make_float4(0.f, 0.f, 0.f, 0.f);
                int gc = wcy0 + r;
                if (gc < ncyc) {
                    const float* xr = &xg[((size_t)gc * s) * 64 + q*4];
                    for (int rr = 0; rr < s; rr++) {
                        float4 v = *(const float4*)&xr[(size_t)rr*64];
                        a.x += v.x; a.y += v.y; a.z += v.z; a.w += v.w;
                    }
                }
                *(float4*)&wss[r*64 + q*4] = a;
            }
        }
        __syncwarp();

        u64 acc[8][2];
        {
            ulonglong2 bb = *(const ulonglong2*)&cs[lane*4];
            #pragma unroll
            for (int r = 0; r < 8; r++) { acc[r][0] = bb.x; acc[r][1] = bb.y; }
        }
        #pragma unroll 2
        for (int k0 = 0; k0 < 64; k0 += 4) {
            ulonglong2 w0 = *(const ulonglong2*)&Bs[(k0+0)*128 + lane*4];
            ulonglong2 w1 = *(const ulonglong2*)&Bs[(k0+1)*128 + lane*4];
            ulonglong2 w2 = *(const ulonglong2*)&Bs[(k0+2)*128 + lane*4];
            ulonglong2 w3 = *(const ulonglong2*)&Bs[(k0+3)*128 + lane*4];
            #pragma unroll
            for (int r = 0; r < 8; r++) {
                float4 iv = *(const float4*)&wss[r*64 + k0];
                u64 p;
                p = pk(iv.x); fma2(acc[r][0], p, w0.x); fma2(acc[r][1], p, w0.y);
                p = pk(iv.y); fma2(acc[r][0], p, w1.x); fma2(acc[r][1], p, w1.y);
                p = pk(iv.z); fma2(acc[r][0], p, w2.x); fma2(acc[r][1], p, w2.y);
                p = pk(iv.w); fma2(acc[r][0], p, w3.x); fma2(acc[r][1], p, w3.y);
            }
        }
        #pragma unroll
        for (int r = 0; r < 8; r++) {
            int gc = wcy0 + r;
            if (full || gc < ncyc) {
                float2 a = up(acc[r][0]), b = up(acc[r][1]);
                float4 o; o.x = a.x; o.y = a.y; o.z = b.x; o.w = b.y;
                *(float4*)&sBg[(size_t)gc*128 + lane*4] = o;
            }
        }
        __syncwarp();
    }
}

// ---------------- cyc2 TENSOR: 384 thr, 12 warps; X staged in upper half of H buffer ----------------
#define OFF_AT   0
#define OFF_W2T  32768
#define OFF_W3T  98304
#define OFF_B2   131072
#define OFF_B3   131584
#define OFF_XH   131840
#define SMEM_CYC2T 230144
#define NB5C 69

__global__ __launch_bounds__(384, 1)
void cyc2_kernel(const float* __restrict__ x5, const float* __restrict__ sB5,
                 const float* __restrict__ A5,
                 const float* __restrict__ x6, const float* __restrict__ sB6,
                 const float* __restrict__ A6,
                 const float* __restrict__ Wc2, const float* __restrict__ bc2,
                 const float* __restrict__ Wc3, const float* __restrict__ bc3,
                 float* __restrict__ outbase)
{
    extern __shared__ char smc[];
    const int tid = threadIdx.x;

    const bool cl5 = blockIdx.x < NB5C;
    const float* xg  = cl5 ? x5 : x6;
    const float* sBg = cl5 ? sB5 : sB6;
    const float* Af  = cl5 ? A5 : A6;
    float* outp      = cl5 ? outbase : (outbase + (size_t)R5*64);
    const int rows   = cl5 ? R5 : R6;
    const int s      = cl5 ? SS5 : SS6;
    const int ntiles = cl5 ? T5T : T6T;
    const int b0c    = cl5 ? blockIdx.x : blockIdx.x - NB5C;
    const int nb     = cl5 ? NB5C : (gridDim.x - NB5C);

    u64* AT  = (u64*)(smc + OFF_AT);
    u64* W2T = (u64*)(smc + OFF_W2T);
    u64* W3T = (u64*)(smc + OFF_W3T);
    float* B2S = (float*)(smc + OFF_B2);
    float* B3S = (float*)(smc + OFF_B3);
    for (int i = tid; i < 128*32; i += 384) {
        int n = i >> 5, p = i & 31;
        AT[n*32 + (p ^ ((n&3)<<2))] = split4(Af[(2*p)*128 + n], Af[(2*p+1)*128 + n]);
    }
    for (int i = tid; i < 128*64; i += 384) {
        int n = i >> 6, p = i & 63;
        W2T[n*64 + (p ^ ((n&3)<<2))] = split4(Wc2[(2*p)*128 + n], Wc2[(2*p+1)*128 + n]);
    }
    for (int i = tid; i < 64*64; i += 384) {
        int n = i >> 6, p = i & 63;
        W3T[n*64 + (p ^ ((n&3)<<2))] = split4(Wc3[(2*p)*64 + n], Wc3[(2*p+1)*64 + n]);
    }
    if (tid < 128) B2S[tid] = bc2[tid];
    else if (tid < 192) B3S[tid-128] = bc3[tid-128];
    __syncthreads();

    const int warp = tid >> 5, lane = tid & 31;
    const int g = lane >> 2, tg = lane & 3;
    const int sw = (g & 3) << 2;
    u64* XH = (u64*)(smc + OFF_XH) + warp*1024;    // [16][64]; X in cols 32..63

    for (int tile = b0c; tile < ntiles; tile += nb) {
        const int row0 = tile * TRW;
        const int wrow0 = row0 + warp*16;
        const bool full = (row0 + TRW <= rows);

        #pragma unroll
        for (int r = 0; r < 16; r++) {
            int gr = wrow0 + r;
            float2 v = make_float2(0.f, 0.f);
            if (full || gr < rows) v = *(const float2*)&xg[(size_t)gr*64 + lane*2];
            XH[r*64 + 32 + (lane ^ ((r&3)<<2))] = split4(v.x, v.y);
        }
        __syncwarp();

        const int ga = wrow0 + g, gb = wrow0 + g + 8;
        const int ca = ((full || ga < rows) ? ga : 0) / s;
        const int cb = ((full || gb < rows) ? gb : 0) / s;
        const float* pA = sBg + (size_t)ca*128;
        const float* pB = sBg + (size_t)cb*128;

        float d[16][4];
        #pragma unroll
        for (int j = 0; j < 16; j++) {
            float2 va = *(const float2*)&pA[j*8 + 2*tg];
            float2 vb = *(const float2*)&pB[j*8 + 2*tg];
            d[j][0] = va.x; d[j][1] = va.y; d[j][2] = vb.x; d[j][3] = vb.y;
        }
        for (int kk = 0; kk < 64; kk += 16) {
            int p0 = (kk >> 1) + tg;
            int c0 = 32 + (p0 ^ sw), c1 = 32 + ((p0 + 4) ^ sw);
            u64 t0 = XH[g*64     + c0];
            u64 t1 = XH[(g+8)*64 + c0];
            u64 t2 = XH[g*64     + c1];
            u64 t3 = XH[(g+8)*64 + c1];
            u32 ah0 = (u32)t0, al0 = (u32)(t0 >> 32);
            u32 ah1 = (u32)t1, al1 = (u32)(t1 >> 32);
            u32 ah2 = (u32)t2, al2 = (u32)(t2 >> 32);
            u32 ah3 = (u32)t3, al3 = (u32)(t3 >> 32);
            int w0i = p0 ^ sw, w1i = (p0 + 4) ^ sw;
            #pragma unroll
            for (int j = 0; j < 16; j++) {
                int n = j*8 + g;
                u64 w0 = AT[n*32 + w0i];
                u64 w1 = AT[n*32 + w1i];
                u32 bh0 = (u32)w0, bl0 = (u32)(w0 >> 32);
                u32 bh1 = (u32)w1, bl1 = (u32)(w1 >> 32);
                mma_bf16(d[j], ah0, ah1, ah2, ah3, bh0, bh1);
                mma_bf16(d[j], ah0, ah1, ah2, ah3, bl0, bl1);
                mma_bf16(d[j], al0, al1, al2, al3, bh0, bh1);
            }
        }
        __syncwarp();
        #pragma unroll
        for (int j = 0; j < 16; j++) {
            float v0 = fmaxf(d[j][0], 0.f), v1 = fmaxf(d[j][1], 0.f);
            float v2 = fmaxf(d[j][2], 0.f), v3 = fmaxf(d[j][3], 0.f);
            int hc = (j*4 + tg) ^ sw;
            XH[g*64     + hc] = split4(v0, v1);
            XH[(g+8)*64 + hc] = split4(v2, v3);
        }
        __syncwarp();

        #pragma unroll
        for (int j = 0; j < 16; j++) {
            float2 bb = *(const float2*)&B2S[j*8 + 2*tg];
            d[j][0] = bb.x; d[j][1] = bb.y; d[j][2] = bb.x; d[j][3] = bb.y;
        }
        for (int kk = 0; kk < 128; kk += 16) {
            int p0 = (kk >> 1) + tg;
            int c0 = p0 ^ sw, c1 = (p0 + 4) ^ sw;
            u64 t0 = XH[g*64     + c0];
            u64 t1 = XH[(g+8)*64 + c0];
            u64 t2 = XH[g*64     + c1];
            u64 t3 = XH[(g+8)*64 + c1];
            u32 ah0 = (u32)t0, al0 = (u32)(t0 >> 32);
            u32 ah1 = (u32)t1, al1 = (u32)(t1 >> 32);
            u32 ah2 = (u32)t2, al2 = (u32)(t2 >> 32);
            u32 ah3 = (u32)t3, al3 = (u32)(t3 >> 32);
            #pragma unroll
            for (int j = 0; j < 16; j++) {
                int n = j*8 + g;
                u64 w0 = W2T[n*64 + c0];
                u64 w1 = W2T[n*64 + c1];
                u32 bh0 = (u32)w0, bl0 = (u32)(w0 >> 32);
                u32 bh1 = (u32)w1, bl1 = (u32)(w1 >> 32);
                mma_bf16(d[j], ah0, ah1, ah2, ah3, bh0, bh1);
                mma_bf16(d[j], ah0, ah1, ah2, ah3, bl0, bl1);
                mma_bf16(d[j], al0, al1, al2, al3, bh0, bh1);
            }
        }
        __syncwarp();
        #pragma unroll
        for (int j = 0; j < 16; j++) {
            float v0 = fmaxf(d[j][0], 0.f), v1 = fmaxf(d[j][1], 0.f);
            float v2 = fmaxf(d[j][2], 0.f), v3 = fmaxf(d[j][3], 0.f);
            int hc = (j*4 + tg) ^ sw;
            XH[g*64     + hc] = split4(v0, v1);
            XH[(g+8)*64 + hc] = split4(v2, v3);
        }
        __syncwarp();

        float e[8][4];
        #pragma unroll
        for (int j = 0; j < 8; j++) {
            float2 bb = *(const float2*)&B3S[j*8 + 2*tg];
            e[j][0] = bb.x; e[j][1] = bb.y; e[j][2] = bb.x; e[j][3] = bb.y;
        }
        for (int kk = 0; kk < 128; kk += 16) {
            int p0 = (kk >> 1) + tg;
            int c0 = p0 ^ sw, c1 = (p0 + 4) ^ sw;
            u64 t0 = XH[g*64     + c0];
            u64 t1 = XH[(g+8)*64 + c0];
            u64 t2 = XH[g*64     + c1];
            u64 t3 = XH[(g+8)*64 + c1];
            u32 ah0 = (u32)t0, al0 = (u32)(t0 >> 32);
            u32 ah1 = (u32)t1, al1 = (u32)(t1 >> 32);
            u32 ah2 = (u32)t2, al2 = (u32)(t2 >> 32);
            u32 ah3 = (u32)t3, al3 = (u32)(t3 >> 32);
            #pragma unroll
            for (int j = 0; j < 8; j++) {
                int n = j*8 + g;
                u64 w0 = W3T[n*64 + c0];
                u64 w1 = W3T[n*64 + c1];
                u32 bh0 = (u32)w0, bl0 = (u32)(w0 >> 32);
                u32 bh1 = (u32)w1, bl1 = (u32)(w1 >> 32);
                mma_bf16(e[j], ah0, ah1, ah2, ah3, bh0, bh1);
                mma_bf16(e[j], ah0, ah1, ah2, ah3, bl0, bl1);
                mma_bf16(e[j], al0, al1, al2, al3, bh0, bh1);
            }
        }
        if (full) {
            #pragma unroll
            for (int j = 0; j < 8; j++) {
                *(float2*)&outp[(size_t)ga*64 + j*8 + 2*tg] = make_float2(e[j][0], e[j][1]);
                *(float2*)&outp[(size_t)gb*64 + j*8 + 2*tg] = make_float2(e[j][2], e[j][3]);
            }
        } else {
            #pragma unroll
            for (int j = 0; j < 8; j++) {
                if (ga < rows) *(float2*)&outp[(size_t)ga*64 + j*8 + 2*tg] = make_float2(e[j][0], e[j][1]);
                if (gb < rows) *(float2*)&outp[(size_t)gb*64 + j*8 + 2*tg] = make_float2(e[j][2], e[j][3]);
            }
        }
        __syncwarp();
    }
}

// ---------------- edge TENSOR: 384 thr, 12 warps, XH aliased ----------------
__global__ __launch_bounds__(384, 1)
void edge_kernel(const float* __restrict__ edge, const int* __restrict__ c2e,
                 const float* __restrict__ cycout,
                 const float* __restrict__ We1, const float* __restrict__ be1,
                 const float* __restrict__ We2, const float* __restrict__ be2,
                 float* __restrict__ outp)
{
    extern __shared__ char smc[];
    const int tid = threadIdx.x;
    u64* W1T = (u64*)(smc + OFF_MW1T);
    u64* W2T = (u64*)(smc + OFF_MW2T);
    float* B1S = (float*)(smc + OFF_MB1);
    float* B2S = (float*)(smc + OFF_MB2);
    for (int i = tid; i < 128*64; i += 384) {
        int n = i >> 6, p = i & 63;
        W1T[n*64 + (p ^ ((n&3)<<2))] = split4(We1[(2*p)*128 + n], We1[(2*p+1)*128 + n]);
    }
    for (int i = tid; i < 64*64; i += 384) {
        int n = i >> 6, p = i & 63;
        W2T[n*64 + (p ^ ((n&3)<<2))] = split4(We2[(2*p)*64 + n], We2[(2*p+1)*64 + n]);
    }
    if (tid < 128) B1S[tid] = be1[tid];
    else if (tid < 192) B2S[tid-128] = be2[tid-128];
    __syncthreads();

    const int warp = tid >> 5, lane = tid & 31;
    const int g = lane >> 2, tg = lane & 3;
    const int sw = (g & 3) << 2;
    u64* XH = (u64*)(smc + OFF_MXH) + warp*1024;
    const int rows = NEDGE;

    for (int tile = blockIdx.x; tile < TET; tile += gridDim.x) {
        const int row0 = tile * TRW;
        const int wrow0 = row0 + warp*16;
        const bool full = (row0 + TRW <= rows);

        #pragma unroll
        for (int r = 0; r < 16; r++) {
            int gr = wrow0 + r;
            int rs = (r & 3) << 2;
            float2 v0 = make_float2(0.f, 0.f);
            float2 v1 = make_float2(0.f, 0.f);
            if (full || gr < rows) {
                v0 = *(const float2*)&edge[(size_t)gr*64 + lane*2];
                int4 ix = *(const int4*)&c2e[gr*4];
                float2 a = *(const float2*)&cycout[(size_t)ix.x*64 + lane*2];
                float2 b = *(const float2*)&cycout[(size_t)ix.y*64 + lane*2];
                float2 c = *(const float2*)&cycout[(size_t)ix.z*64 + lane*2];
                float2 dd = *(const float2*)&cycout[(size_t)ix.w*64 + lane*2];
                v1.x = a.x + b.x + c.x + dd.x;
                v1.y = a.y + b.y + c.y + dd.y;
            }
            XH[r*64 + (lane ^ rs)]        = split4(v0.x, v0.y);
            XH[r*64 + ((32 + lane) ^ rs)] = split4(v1.x, v1.y);
        }
        __syncwarp();

        const int ga = wrow0 + g, gb = wrow0 + g + 8;

        float d[16][4];
        #pragma unroll
        for (int j = 0; j < 16; j++) {
            float2 bb = *(const float2*)&B1S[j*8 + 2*tg];
            d[j][0] = bb.x; d[j][1] = bb.y; d[j][2] = bb.x; d[j][3] = bb.y;
        }
        for (int kk = 0; kk < 128; kk += 16) {
            int p0 = (kk >> 1) + tg;
            int c0 = p0 ^ sw, c1 = (p0 + 4) ^ sw;
            u64 t0 = XH[g*64     + c0];
            u64 t1 = XH[(g+8)*64 + c0];
            u64 t2 = XH[g*64     + c1];
            u64 t3 = XH[(g+8)*64 + c1];
            u32 ah0 = (u32)t0, al0 = (u32)(t0 >> 32);
            u32 ah1 = (u32)t1, al1 = (u32)(t1 >> 32);
            u32 ah2 = (u32)t2, al2 = (u32)(t2 >> 32);
            u32 ah3 = (u32)t3, al3 = (u32)(t3 >> 32);
            #pragma unroll
            for (int j = 0; j < 16; j++) {
                int n = j*8 + g;
                u64 w0 = W1T[n*64 + c0];
                u64 w1 = W1T[n*64 + c1];
                u32 bh0 = (u32)w0, bl0 = (u32)(w0 >> 32);
                u32 bh1 = (u32)w1, bl1 = (u32)(w1 >> 32);
                mma_bf16(d[j], ah0, ah1, ah2, ah3, bh0, bh1);
                mma_bf16(d[j], ah0, ah1, ah2, ah3, bl0, bl1);
                mma_bf16(d[j], al0, al1, al2, al3, bh0, bh1);
            }
        }
        __syncwarp();
        #pragma unroll
        for (int j = 0; j < 16; j++) {
            float v0 = fmaxf(d[j][0], 0.f), v1 = fmaxf(d[j][1], 0.f);
            float v2 = fmaxf(d[j][2], 0.f), v3 = fmaxf(d[j][3], 0.f);
            int hc = (j*4 + tg) ^ sw;
            XH[g*64     + hc] = split4(v0, v1);
            XH[(g+8)*64 + hc] = split4(v2, v3);
        }
        __syncwarp();

        float e[8][4];
        #pragma unroll
        for (int j = 0; j < 8; j++) {
            float2 bb = *(const float2*)&B2S[j*8 + 2*tg];
            e[j][0] = bb.x; e[j][1] = bb.y; e[j][2] = bb.x; e[j][3] = bb.y;
        }
        for (int kk = 0; kk < 128; kk += 16) {
            int p0 = (kk >> 1) + tg;
            int c0 = p0 ^ sw, c1 = (p0 + 4) ^ sw;
            u64 t0 = XH[g*64     + c0];
            u64 t1 = XH[(g+8)*64 + c0];
            u64 t2 = XH[g*64     + c1];
            u64 t3 = XH[(g+8)*64 + c1];
            u32 ah0 = (u32)t0, al0 = (u32)(t0 >> 32);
            u32 ah1 = (u32)t1, al1 = (u32)(t1 >> 32);
            u32 ah2 = (u32)t2, al2 = (u32)(t2 >> 32);
            u32 ah3 = (u32)t3, al3 = (u32)(t3 >> 32);
            #pragma unroll
            for (int j = 0; j < 8; j++) {
                int n = j*8 + g;
                u64 w0 = W2T[n*64 + c0];
                u64 w1 = W2T[n*64 + c1];
                u32 bh0 = (u32)w0, bl0 = (u32)(w0 >> 32);
                u32 bh1 = (u32)w1, bl1 = (u32)(w1 >> 32);
                mma_bf16(e[j], ah0, ah1, ah2, ah3, bh0, bh1);
                mma_bf16(e[j], ah0, ah1, ah2, ah3, bl0, bl1);
                mma_bf16(e[j], al0, al1, al2, al3, bh0, bh1);
            }
        }
        if (full) {
            #pragma unroll
            for (int j = 0; j < 8; j++) {
                *(float2*)&outp[(size_t)ga*64 + j*8 + 2*tg] = make_float2(e[j][0], e[j][1]);
                *(float2*)&outp[(size_t)gb*64 + j*8 + 2*tg] = make_float2(e[j][2], e[j][3]);
            }
        } else {
            #pragma unroll
            for (int j = 0; j < 8; j++) {
                if (ga < rows) *(float2*)&outp[(size_t)ga*64 + j*8 + 2*tg] = make_float2(e[j][0], e[j][1]);
                if (gb < rows) *(float2*)&outp[(size_t)gb*64 + j*8 + 2*tg] = make_float2(e[j][2], e[j][3]);
            }
        }
        __syncwarp();
    }
}

// ---------------- launch ----------------
extern "C" void kernel_launch(void* const* d_in, const int* in_sizes, int n_in,
                              void* d_out, int out_size)
{
    const float* edge_rep = (const float*)d_in[0];
    const float* cyc5 = (const float*)d_in[1];
    const float* cyc6 = (const float*)d_in[2];
    const int*   e2c5 = (const int*)d_in[3];
    const int*   e2c6 = (const int*)d_in[4];
    const int*   c2e  = (const int*)d_in[5];
    const float* W1  = (const float*)d_in[6];
    const float* b1  = (const float*)d_in[7];
    const float* W2  = (const float*)d_in[8];
    const float* b2  = (const float*)d_in[9];
    const float* Wc1 = (const float*)d_in[10];
    const float* bc1 = (const float*)d_in[11];
    const float* Wc2 = (const float*)d_in[12];
    const float* bc2 = (const float*)d_in[13];
    const float* Wc3 = (const float*)d_in[14];
    const float* bc3 = (const float*)d_in[15];
    const float* We1 = (const float*)d_in[16];
    const float* be1 = (const float*)d_in[17];
    const float* We2 = (const float*)d_in[18];
    const float* be2 = (const float*)d_in[19];
    const float* Wid5  = (const float*)d_in[20];
    const float* Wsum5 = (const float*)d_in[21];
    const float* bab5  = (const float*)d_in[22];
    const float* Wid6  = (const float*)d_in[23];
    const float* Wsum6 = (const float*)d_in[24];
    const float* bab6  = (const float*)d_in[25];
    float* out = (float*)d_out;

    float *x5, *x6, *sB5, *sB6, *A5, *B5, *c5, *A6, *B6, *c6;
    cudaGetSymbolAddress((void**)&x5,  g_x5);
    cudaGetSymbolAddress((void**)&x6,  g_x6);
    cudaGetSymbolAddress((void**)&sB5, g_sB5);
    cudaGetSymbolAddress((void**)&sB6, g_sB6);
    cudaGetSymbolAddress((void**)&A5,  g_A5);
    cudaGetSymbolAddress((void**)&B5,  g_B5);
    cudaGetSymbolAddress((void**)&c5,  g_c5);
    cudaGetSymbolAddress((void**)&A6,  g_A6);
    cudaGetSymbolAddress((void**)&B6,  g_B6);
    cudaGetSymbolAddress((void**)&c6,  g_c6);

    cudaFuncSetAttribute(mlp2_kernel, cudaFuncAttributeMaxDynamicSharedMemorySize, SMEM_MT);
    cudaFuncSetAttribute(edge_kernel, cudaFuncAttributeMaxDynamicSharedMemorySize, SMEM_MT);
    cudaFuncSetAttribute(cyc2_kernel, cudaFuncAttributeMaxDynamicSharedMemorySize, SMEM_CYC2T);
    cudaFuncSetAttribute(sB_kernel,   cudaFuncAttributeMaxDynamicSharedMemorySize, SMEM_SB);

    const int NBLK = 152;

    fold_all_kernel<<<130, 128>>>(Wc1, bc1, Wid5, Wsum5, bab5, Wid6, Wsum6, bab6,
                                  A5, B5, c5, A6, B6, c6);

    mlp2_kernel<<<NBLK, 384, SMEM_MT>>>(cyc5, e2c5, cyc6, e2c6, edge_rep,
                                        W1, b1, W2, b2, x5, x6);

    sB_kernel<<<NBLK, 512, SMEM_SB>>>(x5, x6, B5, c5, B6, c6, sB5, sB6);

    cyc2_kernel<<<NBLK, 384, SMEM_CYC2T>>>(x5, sB5, A5, x6, sB6, A6,
                                           Wc2, bc2, Wc3, bc3,
                                           out + (size_t)NEDGE*64);

    edge_kernel<<<NBLK, 384, SMEM_MT>>>(edge_rep, c2e, out + (size_t)NEDGE*64,
                                        We1, be1, We2, be2, out);
}

// round 17
// speedup vs baseline: 1.5283x; 1.0766x over previous
#include <cuda_runtime.h>
#include <cuda_bf16.h>

#define DD 64
#define NEDGE 200000
#define NC5 30000
#define SS5 5
#define NC6 30000
#define SS6 6
#define R5 (NC5*SS5)
#define R6 (NC6*SS6)

typedef unsigned long long u64;
typedef unsigned int u32;

// ---------------- packed f32x2 helpers (Blackwell) ----------------
__device__ __forceinline__ u64 pk(float v) {
    u64 r; asm("mov.b64 %0, {%1, %1};" : "=l"(r) : "f"(v)); return r;
}
__device__ __forceinline__ void fma2(u64& d, u64 a, u64 b) {
    asm("fma.rn.f32x2 %0, %1, %2, %0;" : "+l"(d) : "l"(a), "l"(b));
}
__device__ __forceinline__ float2 up(u64 v) {
    float2 r; asm("mov.b64 {%0, %1}, %2;" : "=f"(r.x), "=f"(r.y) : "l"(v)); return r;
}

// ---------------- bf16 split helpers ----------------
// interleaved u64: low u32 = {h(x) | h(y)<<16}, high u32 = {l(x) | l(y)<<16}
__device__ __forceinline__ u64 split4(float x, float y) {
    __nv_bfloat16 bx = __float2bfloat16_rn(x), by = __float2bfloat16_rn(y);
    float fx = __bfloat162float(bx), fy = __bfloat162float(by);
    __nv_bfloat16 cx = __float2bfloat16_rn(x - fx), cy = __float2bfloat16_rn(y - fy);
    u32 hi = ((u32)(*(unsigned short*)&by) << 16) | *(unsigned short*)&bx;
    u32 lo = ((u32)(*(unsigned short*)&cy) << 16) | *(unsigned short*)&cx;
    return ((u64)lo << 32) | hi;
}
__device__ __forceinline__ void mma_bf16(float d[4], u32 a0, u32 a1, u32 a2, u32 a3,
                                         u32 b0, u32 b1) {
    asm volatile(
        "mma.sync.aligned.m16n8k16.row.col.f32.bf16.bf16.f32 "
        "{%0,%1,%2,%3},{%4,%5,%6,%7},{%8,%9},{%0,%1,%2,%3};"
        : "+f"(d[0]), "+f"(d[1]), "+f"(d[2]), "+f"(d[3])
        : "r"(a0), "r"(a1), "r"(a2), "r"(a3), "r"(b0), "r"(b1));
}

// ---------------- scratch ----------------
__device__ float g_x5[R5*DD];
__device__ float g_x6[R6*DD];
__device__ float g_sB5[NC5*128];
__device__ float g_sB6[NC6*128];
__device__ float g_A5[64*128];
__device__ float g_B5[64*128];
__device__ float g_c5[128];
__device__ float g_A6[64*128];
__device__ float g_B6[64*128];
__device__ float g_c6[128];

// ---------------- weight folding ----------------
__global__ __launch_bounds__(128)
void fold_all_kernel(const float* __restrict__ Wc1, const float* __restrict__ bc1,
                     const float* __restrict__ Wid5, const float* __restrict__ Wsum5,
                     const float* __restrict__ bab5,
                     const float* __restrict__ Wid6, const float* __restrict__ Wsum6,
                     const float* __restrict__ bab6,
                     float* __restrict__ A5, float* __restrict__ B5, float* __restrict__ c5,
                     float* __restrict__ A6, float* __restrict__ B6, float* __restrict__ c6)
{
    int b = blockIdx.x;
    int sz = b / 65;
    int r  = b % 65;
    const float* Wid  = sz ? Wid6  : Wid5;
    const float* Wsum = sz ? Wsum6 : Wsum5;
    const float* bab  = sz ? bab6  : bab5;
    float* A = sz ? A6 : A5;
    float* B = sz ? B6 : B5;
    float* c = sz ? c6 : c5;

    __shared__ float wa[256], wb[256];
    int j = threadIdx.x;
    if (r < 64) {
        wa[j]       = Wid[r*256 + j];
        wa[j + 128] = Wid[r*256 + 128 + j];
        wb[j]       = Wsum[r*256 + j];
        wb[j + 128] = Wsum[r*256 + 128 + j];
    } else {
        wa[j]       = bab[j];
        wa[j + 128] = bab[128 + j];
        wb[j] = 0.f; wb[j + 128] = 0.f;
    }
    __syncthreads();

    float accA, accB;
    if (r < 64) { accA = Wc1[r*128 + j]; accB = Wc1[(64 + r)*128 + j]; }
    else        { accA = bc1[j];         accB = 0.f; }

    const float* base = Wc1 + 128*128 + j;
    #pragma unroll 8
    for (int m = 0; m < 256; m++) {
        float wc = __ldg(&base[m*128]);
        accA += wa[m] * wc;
        accB += wb[m] * wc;
    }
    if (r < 64) { A[r*128 + j] = accA; B[r*128 + j] = accB; }
    else        { c[j] = accA; }
}

// ======== tensor kernels: 384 threads, 12 warps x 16 rows = 192-row tiles ========
#define TRW 192
#define T5T ((R5 + TRW - 1)/TRW)
#define T6T ((R6 + TRW - 1)/TRW)
#define TET ((NEDGE + TRW - 1)/TRW)
#define NB5M 69

// -------- mlp2/edge smem: W1T 65536, W2T 32768, b 768, X 12*8192 --------
#define OFF_MW1T 0
#define OFF_MW2T 65536
#define OFF_MB1  98304
#define OFF_MB2  98816
#define OFF_MX   99072
#define SMEM_MT  197376

// ---------------- mlp2 TENSOR: x = relu(relu([cyc|e-gather]@W1+b1)@W2+b2) ----------------
__global__ __launch_bounds__(384, 1)
void mlp2_kernel(const float* __restrict__ cyc5, const int* __restrict__ e2c5,
                 const float* __restrict__ cyc6, const int* __restrict__ e2c6,
                 const float* __restrict__ edge,
                 const float* __restrict__ W1, const float* __restrict__ b1,
                 const float* __restrict__ W2, const float* __restrict__ b2,
                 float* __restrict__ x5, float* __restrict__ x6)
{
    extern __shared__ char smc[];
    const int tid = threadIdx.x;
    u64* W1T = (u64*)(smc + OFF_MW1T);
    u64* W2T = (u64*)(smc + OFF_MW2T);
    float* B1S = (float*)(smc + OFF_MB1);
    float* B2S = (float*)(smc + OFF_MB2);
    for (int i = tid; i < 128*64; i += 384) {
        int n = i >> 6, p = i & 63;
        W1T[n*64 + (p ^ ((n&3)<<2))] = split4(W1[(2*p)*128 + n], W1[(2*p+1)*128 + n]);
    }
    for (int i = tid; i < 64*64; i += 384) {
        int n = i >> 6, p = i & 63;
        W2T[n*64 + (p ^ ((n&3)<<2))] = split4(W2[(2*p)*64 + n], W2[(2*p+1)*64 + n]);
    }
    if (tid < 128) B1S[tid] = b1[tid];
    else if (tid < 192) B2S[tid-128] = b2[tid-128];
    __syncthreads();

    const bool cl5 = blockIdx.x < NB5M;
    const float* cyc = cl5 ? cyc5 : cyc6;
    const int*   e2c = cl5 ? e2c5 : e2c6;
    float*      xout = cl5 ? x5  : x6;
    const int rows   = cl5 ? R5 : R6;
    const int ntiles = cl5 ? T5T : T6T;
    const int b0     = cl5 ? blockIdx.x : blockIdx.x - NB5M;
    const int nb     = cl5 ? NB5M : (gridDim.x - NB5M);

    const int warp = tid >> 5, lane = tid & 31;
    const int g = lane >> 2, tg = lane & 3;
    const int sw = (g & 3) << 2;
    u64* XI = (u64*)(smc + OFF_MX) + warp*1024;   // [16][64]

    for (int tile = b0; tile < ntiles; tile += nb) {
        const int row0 = tile * TRW;
        const int wrow0 = row0 + warp*16;
        const bool full = (row0 + TRW <= rows);

        // ---- stage [cyc | edge-gather] split, swizzled
        #pragma unroll
        for (int r = 0; r < 16; r++) {
            int gr = wrow0 + r;
            int rs = (r & 3) << 2;
            float2 v0 = make_float2(0.f, 0.f);
            float2 v1 = make_float2(0.f, 0.f);
            if (full || gr < rows) {
                v0 = *(const float2*)&cyc[(size_t)gr*64 + lane*2];
                int2 e = *(const int2*)&e2c[gr*2];
                float2 a = *(const float2*)&edge[(size_t)e.x*64 + lane*2];
                float2 c2 = *(const float2*)&edge[(size_t)e.y*64 + lane*2];
                v1.x = a.x + c2.x; v1.y = a.y + c2.y;
            }
            XI[r*64 + (lane ^ rs)]        = split4(v0.x, v0.y);
            XI[r*64 + ((32 + lane) ^ rs)] = split4(v1.x, v1.y);
        }
        __syncwarp();

        const int ga = wrow0 + g, gb = wrow0 + g + 8;

        // ---------- h = relu(in @ W1 + b1) : K=128, 16 n-tiles ----------
        float d[16][4];
        #pragma unroll
        for (int j = 0; j < 16; j++) {
            float2 bb = *(const float2*)&B1S[j*8 + 2*tg];
            d[j][0] = bb.x; d[j][1] = bb.y; d[j][2] = bb.x; d[j][3] = bb.y;
        }
        for (int kk = 0; kk < 128; kk += 16) {
            int p0 = (kk >> 1) + tg;
            int c0 = p0 ^ sw, c1 = (p0 + 4) ^ sw;
            u64 t0 = XI[g*64     + c0];
            u64 t1 = XI[(g+8)*64 + c0];
            u64 t2 = XI[g*64     + c1];
            u64 t3 = XI[(g+8)*64 + c1];
            u32 ah0 = (u32)t0, al0 = (u32)(t0 >> 32);
            u32 ah1 = (u32)t1, al1 = (u32)(t1 >> 32);
            u32 ah2 = (u32)t2, al2 = (u32)(t2 >> 32);
            u32 ah3 = (u32)t3, al3 = (u32)(t3 >> 32);
            #pragma unroll
            for (int j = 0; j < 16; j++) {
                int n = j*8 + g;
                u64 w0 = W1T[n*64 + c0];
                u64 w1 = W1T[n*64 + c1];
                u32 bh0 = (u32)w0, bl0 = (u32)(w0 >> 32);
                u32 bh1 = (u32)w1, bl1 = (u32)(w1 >> 32);
                mma_bf16(d[j], ah0, ah1, ah2, ah3, bh0, bh1);
                mma_bf16(d[j], ah0, ah1, ah2, ah3, bl0, bl1);
                mma_bf16(d[j], al0, al1, al2, al3, bh0, bh1);
            }
        }
        // ---- relu + split into REGISTERS (D-frag == next A-frag layout)
        u64 ph[16][2];
        #pragma unroll
        for (int j = 0; j < 16; j++) {
            ph[j][0] = split4(fmaxf(d[j][0], 0.f), fmaxf(d[j][1], 0.f)); // row g
            ph[j][1] = split4(fmaxf(d[j][2], 0.f), fmaxf(d[j][3], 0.f)); // row g+8
        }

        // ---------- x = relu(h @ W2 + b2) : K=128, 8 n-tiles, A from regs ----------
        float e[8][4];
        #pragma unroll
        for (int j = 0; j < 8; j++) {
            float2 bb = *(const float2*)&B2S[j*8 + 2*tg];
            e[j][0] = bb.x; e[j][1] = bb.y; e[j][2] = bb.x; e[j][3] = bb.y;
        }
        #pragma unroll
        for (int kk = 0; kk < 128; kk += 16) {
            int jj = kk >> 3;
            int p0 = (kk >> 1) + tg;
            int c0 = p0 ^ sw, c1 = (p0 + 4) ^ sw;
            u64 t0 = ph[jj][0];
            u64 t1 = ph[jj][1];
            u64 t2 = ph[jj+1][0];
            u64 t3 = ph[jj+1][1];
            u32 ah0 = (u32)t0, al0 = (u32)(t0 >> 32);
            u32 ah1 = (u32)t1, al1 = (u32)(t1 >> 32);
            u32 ah2 = (u32)t2, al2 = (u32)(t2 >> 32);
            u32 ah3 = (u32)t3, al3 = (u32)(t3 >> 32);
            #pragma unroll
            for (int j = 0; j < 8; j++) {
                int n = j*8 + g;
                u64 w0 = W2T[n*64 + c0];
                u64 w1 = W2T[n*64 + c1];
                u32 bh0 = (u32)w0, bl0 = (u32)(w0 >> 32);
                u32 bh1 = (u32)w1, bl1 = (u32)(w1 >> 32);
                mma_bf16(e[j], ah0, ah1, ah2, ah3, bh0, bh1);
                mma_bf16(e[j], ah0, ah1, ah2, ah3, bl0, bl1);
                mma_bf16(e[j], al0, al1, al2, al3, bh0, bh1);
            }
        }
        if (full) {
            #pragma unroll
            for (int j = 0; j < 8; j++) {
                *(float2*)&xout[(size_t)ga*64 + j*8 + 2*tg] =
                    make_float2(fmaxf(e[j][0], 0.f), fmaxf(e[j][1], 0.f));
                *(float2*)&xout[(size_t)gb*64 + j*8 + 2*tg] =
                    make_float2(fmaxf(e[j][2], 0.f), fmaxf(e[j][3], 0.f));
            }
        } else {
            #pragma unroll
            for (int j = 0; j < 8; j++) {
                if (ga < rows) *(float2*)&xout[(size_t)ga*64 + j*8 + 2*tg] =
                    make_float2(fmaxf(e[j][0], 0.f), fmaxf(e[j][1], 0.f));
                if (gb < rows) *(float2*)&xout[(size_t)gb*64 + j*8 + 2*tg] =
                    make_float2(fmaxf(e[j][2], 0.f), fmaxf(e[j][3], 0.f));
            }
        }
        __syncwarp();   // all lanes done reading X before next tile's staging
    }
}

// ---------------- sB (merged, scalar — unchanged) ----------------
#define SMEM_SB ((64*128 + 128 + 128*64) * 4)
#define T5S ((NC5 + 127)/128)
#define T6S ((NC6 + 127)/128)
#define NB5S 76

__global__ __launch_bounds__(512, 1)
void sB_kernel(const float* __restrict__ x5, const float* __restrict__ x6,
               const float* __restrict__ B5, const float* __restrict__ c5,
               const float* __restrict__ B6, const float* __restrict__ c6,
               float* __restrict__ sB5, float* __restrict__ sB6)
{
    extern __shared__ float sm[];
    float* Bs = sm;
    float* cs = Bs + 64*128;
    float* ss = cs + 128;
    const int tid = threadIdx.x;

    const bool cl5 = blockIdx.x < NB5S;
    const float* xg = cl5 ? x5 : x6;
    const float* Bf = cl5 ? B5 : B6;
    const float* cf = cl5 ? c5 : c6;
    float*      sBg = cl5 ? sB5 : sB6;
    const int s      = cl5 ? SS5 : SS6;
    const int ncyc   = cl5 ? NC5 : NC6;
    const int ntiles = cl5 ? T5S : T6S;
    const int b0     = cl5 ? blockIdx.x : blockIdx.x - NB5S;
    const int nb     = cl5 ? NB5S : (gridDim.x - NB5S);

    for (int i = tid; i < 64*128; i += 512) Bs[i] = Bf[i];
    if (tid < 128) cs[tid] = cf[tid];
    __syncthreads();

    const int warp = tid >> 5, lane = tid & 31;
    float* wss = &ss[(warp*8)*64];

    for (int tile = b0; tile < ntiles; tile += nb) {
        const int cy0 = tile << 7;
        const int wcy0 = cy0 + warp*8;
        const bool full = (cy0 + 128 <= ncyc);
        if (full) {
            #pragma unroll
            for (int t = 0; t < 4; t++) {
                int i = t*32 + lane;
                int r = i >> 4, q = i & 15;
                int gc = wcy0 + r;
                float4 a = make_float4(0.f, 0.f, 0.f, 0.f);
                const float* xr = &xg[((size_t)gc * s) * 64 + q*4];
                for (int rr = 0; rr < s; rr++) {
                    float4 v = *(const float4*)&xr[(size_t)rr*64];
                    a.x += v.x; a.y += v.y; a.z += v.z; a.w += v.w;
                }
                *(float4*)&wss[r*64 + q*4] = a;
            }
        } else {
            #pragma unroll
            for (int t = 0; t < 4; t++) {
                int i = t*32 + lane;
                int r = i >> 4, q = i & 15;
                float4 a = make_float4(0.f, 0.f, 0.f, 0.f);
                int gc = wcy0 + r;
                if (gc < ncyc) {
                    const float* xr = &xg[((size_t)gc * s) * 64 + q*4];
                    for (int rr = 0; rr < s; rr++) {
                        float4 v = *(const float4*)&xr[(size_t)rr*64];
                        a.x += v.x; a.y += v.y; a.z += v.z; a.w += v.w;
                    }
                }
                *(float4*)&wss[r*64 + q*4] = a;
            }
        }
        __syncwarp();

        u64 acc[8][2];
        {
            ulonglong2 bb = *(const ulonglong2*)&cs[lane*4];
            #pragma unroll
            for (int r = 0; r < 8; r++) { acc[r][0] = bb.x; acc[r][1] = bb.y; }
        }
        #pragma unroll 2
        for (int k0 = 0; k0 < 64; k0 += 4) {
            ulonglong2 w0 = *(const ulonglong2*)&Bs[(k0+0)*128 + lane*4];
            ulonglong2 w1 = *(const ulonglong2*)&Bs[(k0+1)*128 + lane*4];
            ulonglong2 w2 = *(const ulonglong2*)&Bs[(k0+2)*128 + lane*4];
            ulonglong2 w3 = *(const ulonglong2*)&Bs[(k0+3)*128 + lane*4];
            #pragma unroll
            for (int r = 0; r < 8; r++) {
                float4 iv = *(const float4*)&wss[r*64 + k0];
                u64 p;
                p = pk(iv.x); fma2(acc[r][0], p, w0.x); fma2(acc[r][1], p, w0.y);
                p = pk(iv.y); fma2(acc[r][0], p, w1.x); fma2(acc[r][1], p, w1.y);
                p = pk(iv.z); fma2(acc[r][0], p, w2.x); fma2(acc[r][1], p, w2.y);
                p = pk(iv.w); fma2(acc[r][0], p, w3.x); fma2(acc[r][1], p, w3.y);
            }
        }
        #pragma unroll
        for (int r = 0; r < 8; r++) {
            int gc = wcy0 + r;
            if (full || gc < ncyc) {
                float2 a = up(acc[r][0]), b = up(acc[r][1]);
                float4 o; o.x = a.x; o.y = a.y; o.z = b.x; o.w = b.y;
                *(float4*)&sBg[(size_t)gc*128 + lane*4] = o;
            }
        }
        __syncwarp();
    }
}

// ---------------- cyc2 TENSOR: register-passed h1/h2, X-only smem [16][32] ----------------
#define OFF_AT   0
#define OFF_W2T  32768
#define OFF_W3T  98304
#define OFF_B2   131072
#define OFF_B3   131584
#define OFF_X    131840
#define SMEM_CYC2T (131840 + 12*4096)
#define NB5C 69

__global__ __launch_bounds__(384, 1)
void cyc2_kernel(const float* __restrict__ x5, const float* __restrict__ sB5,
                 const float* __restrict__ A5,
                 const float* __restrict__ x6, const float* __restrict__ sB6,
                 const float* __restrict__ A6,
                 const float* __restrict__ Wc2, const float* __restrict__ bc2,
                 const float* __restrict__ Wc3, const float* __restrict__ bc3,
                 float* __restrict__ outbase)
{
    extern __shared__ char smc[];
    const int tid = threadIdx.x;

    const bool cl5 = blockIdx.x < NB5C;
    const float* xg  = cl5 ? x5 : x6;
    const float* sBg = cl5 ? sB5 : sB6;
    const float* Af  = cl5 ? A5 : A6;
    float* outp      = cl5 ? outbase : (outbase + (size_t)R5*64);
    const int rows   = cl5 ? R5 : R6;
    const int s      = cl5 ? SS5 : SS6;
    const int ntiles = cl5 ? T5T : T6T;
    const int b0c    = cl5 ? blockIdx.x : blockIdx.x - NB5C;
    const int nb     = cl5 ? NB5C : (gridDim.x - NB5C);

    u64* AT  = (u64*)(smc + OFF_AT);
    u64* W2T = (u64*)(smc + OFF_W2T);
    u64* W3T = (u64*)(smc + OFF_W3T);
    float* B2S = (float*)(smc + OFF_B2);
    float* B3S = (float*)(smc + OFF_B3);
    for (int i = tid; i < 128*32; i += 384) {
        int n = i >> 5, p = i & 31;
        AT[n*32 + (p ^ ((n&3)<<2))] = split4(Af[(2*p)*128 + n], Af[(2*p+1)*128 + n]);
    }
    for (int i = tid; i < 128*64; i += 384) {
        int n = i >> 6, p = i & 63;
        W2T[n*64 + (p ^ ((n&3)<<2))] = split4(Wc2[(2*p)*128 + n], Wc2[(2*p+1)*128 + n]);
    }
    for (int i = tid; i < 64*64; i += 384) {
        int n = i >> 6, p = i & 63;
        W3T[n*64 + (p ^ ((n&3)<<2))] = split4(Wc3[(2*p)*64 + n], Wc3[(2*p+1)*64 + n]);
    }
    if (tid < 128) B2S[tid] = bc2[tid];
    else if (tid < 192) B3S[tid-128] = bc3[tid-128];
    __syncthreads();

    const int warp = tid >> 5, lane = tid & 31;
    const int g = lane >> 2, tg = lane & 3;
    const int sw = (g & 3) << 2;
    u64* XI = (u64*)(smc + OFF_X) + warp*512;      // [16][32]

    for (int tile = b0c; tile < ntiles; tile += nb) {
        const int row0 = tile * TRW;
        const int wrow0 = row0 + warp*16;
        const bool full = (row0 + TRW <= rows);

        // stage x (K=64, 32 kpairs), swizzled
        #pragma unroll
        for (int r = 0; r < 16; r++) {
            int gr = wrow0 + r;
            float2 v = make_float2(0.f, 0.f);
            if (full || gr < rows) v = *(const float2*)&xg[(size_t)gr*64 + lane*2];
            XI[r*32 + (lane ^ ((r&3)<<2))] = split4(v.x, v.y);
        }
        __syncwarp();

        const int ga = wrow0 + g, gb = wrow0 + g + 8;
        const int ca = ((full || ga < rows) ? ga : 0) / s;
        const int cb = ((full || gb < rows) ? gb : 0) / s;
        const float* pA = sBg + (size_t)ca*128;
        const float* pB = sBg + (size_t)cb*128;

        // ---------- h1 = relu(x @ Afold + sB[cid]) : K=64 ----------
        float d[16][4];
        #pragma unroll
        for (int j = 0; j < 16; j++) {
            float2 va = *(const float2*)&pA[j*8 + 2*tg];
            float2 vb = *(const float2*)&pB[j*8 + 2*tg];
            d[j][0] = va.x; d[j][1] = va.y; d[j][2] = vb.x; d[j][3] = vb.y;
        }
        for (int kk = 0; kk < 64; kk += 16) {
            int p0 = (kk >> 1) + tg;
            int c0 = p0 ^ sw, c1 = (p0 + 4) ^ sw;
            u64 t0 = XI[g*32     + c0];
            u64 t1 = XI[(g+8)*32 + c0];
            u64 t2 = XI[g*32     + c1];
            u64 t3 = XI[(g+8)*32 + c1];
            u32 ah0 = (u32)t0, al0 = (u32)(t0 >> 32);
            u32 ah1 = (u32)t1, al1 = (u32)(t1 >> 32);
            u32 ah2 = (u32)t2, al2 = (u32)(t2 >> 32);
            u32 ah3 = (u32)t3, al3 = (u32)(t3 >> 32);
            #pragma unroll
            for (int j = 0; j < 16; j++) {
                int n = j*8 + g;
                u64 w0 = AT[n*32 + c0];
                u64 w1 = AT[n*32 + c1];
                u32 bh0 = (u32)w0, bl0 = (u32)(w0 >> 32);
                u32 bh1 = (u32)w1, bl1 = (u32)(w1 >> 32);
                mma_bf16(d[j], ah0, ah1, ah2, ah3, bh0, bh1);
                mma_bf16(d[j], ah0, ah1, ah2, ah3, bl0, bl1);
                mma_bf16(d[j], al0, al1, al2, al3, bh0, bh1);
            }
        }
        // relu + split into registers
        u64 ph[16][2];
        #pragma unroll
        for (int j = 0; j < 16; j++) {
            ph[j][0] = split4(fmaxf(d[j][0], 0.f), fmaxf(d[j][1], 0.f));
            ph[j][1] = split4(fmaxf(d[j][2], 0.f), fmaxf(d[j][3], 0.f));
        }

        // ---------- h2 = relu(h1 @ Wc2 + bc2) : K=128, A from regs ----------
        #pragma unroll
        for (int j = 0; j < 16; j++) {
            float2 bb = *(const float2*)&B2S[j*8 + 2*tg];
            d[j][0] = bb.x; d[j][1] = bb.y; d[j][2] = bb.x; d[j][3] = bb.y;
        }
        #pragma unroll
        for (int kk = 0; kk < 128; kk += 16) {
            int jj = kk >> 3;
            int p0 = (kk >> 1) + tg;
            int c0 = p0 ^ sw, c1 = (p0 + 4) ^ sw;
            u64 t0 = ph[jj][0];
            u64 t1 = ph[jj][1];
            u64 t2 = ph[jj+1][0];
            u64 t3 = ph[jj+1][1];
            u32 ah0 = (u32)t0, al0 = (u32)(t0 >> 32);
            u32 ah1 = (u32)t1, al1 = (u32)(t1 >> 32);
            u32 ah2 = (u32)t2, al2 = (u32)(t2 >> 32);
            u32 ah3 = (u32)t3, al3 = (u32)(t3 >> 32);
            #pragma unroll
            for (int j = 0; j < 16; j++) {
                int n = j*8 + g;
                u64 w0 = W2T[n*64 + c0];
                u64 w1 = W2T[n*64 + c1];
                u32 bh0 = (u32)w0, bl0 = (u32)(w0 >> 32);
                u32 bh1 = (u32)w1, bl1 = (u32)(w1 >> 32);
                mma_bf16(d[j], ah0, ah1, ah2, ah3, bh0, bh1);
                mma_bf16(d[j], ah0, ah1, ah2, ah3, bl0, bl1);
                mma_bf16(d[j], al0, al1, al2, al3, bh0, bh1);
            }
        }
        // relu + split into registers (reuse ph)
        #pragma unroll
        for (int j = 0; j < 16; j++) {
            ph[j][0] = split4(fmaxf(d[j][0], 0.f), fmaxf(d[j][1], 0.f));
            ph[j][1] = split4(fmaxf(d[j][2], 0.f), fmaxf(d[j][3], 0.f));
        }

        // ---------- out = h2 @ Wc3 + bc3 : K=128, 8 n-tiles, A from regs ----------
        float e[8][4];
        #pragma unroll
        for (int j = 0; j < 8; j++) {
            float2 bb = *(const float2*)&B3S[j*8 + 2*tg];
            e[j][0] = bb.x; e[j][1] = bb.y; e[j][2] = bb.x; e[j][3] = bb.y;
        }
        #pragma unroll
        for (int kk = 0; kk < 128; kk += 16) {
            int jj = kk >> 3;
            int p0 = (kk >> 1) + tg;
            int c0 = p0 ^ sw, c1 = (p0 + 4) ^ sw;
            u64 t0 = ph[jj][0];
            u64 t1 = ph[jj][1];
            u64 t2 = ph[jj+1][0];
            u64 t3 = ph[jj+1][1];
            u32 ah0 = (u32)t0, al0 = (u32)(t0 >> 32);
            u32 ah1 = (u32)t1, al1 = (u32)(t1 >> 32);
            u32 ah2 = (u32)t2, al2 = (u32)(t2 >> 32);
            u32 ah3 = (u32)t3, al3 = (u32)(t3 >> 32);
            #pragma unroll
            for (int j = 0; j < 8; j++) {
                int n = j*8 + g;
                u64 w0 = W3T[n*64 + c0];
                u64 w1 = W3T[n*64 + c1];
                u32 bh0 = (u32)w0, bl0 = (u32)(w0 >> 32);
                u32 bh1 = (u32)w1, bl1 = (u32)(w1 >> 32);
                mma_bf16(e[j], ah0, ah1, ah2, ah3, bh0, bh1);
                mma_bf16(e[j], ah0, ah1, ah2, ah3, bl0, bl1);
                mma_bf16(e[j], al0, al1, al2, al3, bh0, bh1);
            }
        }
        if (full) {
            #pragma unroll
            for (int j = 0; j < 8; j++) {
                *(float2*)&outp[(size_t)ga*64 + j*8 + 2*tg] = make_float2(e[j][0], e[j][1]);
                *(float2*)&outp[(size_t)gb*64 + j*8 + 2*tg] = make_float2(e[j][2], e[j][3]);
            }
        } else {
            #pragma unroll
            for (int j = 0; j < 8; j++) {
                if (ga < rows) *(float2*)&outp[(size_t)ga*64 + j*8 + 2*tg] = make_float2(e[j][0], e[j][1]);
                if (gb < rows) *(float2*)&outp[(size_t)gb*64 + j*8 + 2*tg] = make_float2(e[j][2], e[j][3]);
            }
        }
        __syncwarp();
    }
}

// ---------------- edge TENSOR: register-passed h ----------------
__global__ __launch_bounds__(384, 1)
void edge_kernel(const float* __restrict__ edge, const int* __restrict__ c2e,
                 const float* __restrict__ cycout,
                 const float* __restrict__ We1, const float* __restrict__ be1,
                 const float* __restrict__ We2, const float* __restrict__ be2,
                 float* __restrict__ outp)
{
    extern __shared__ char smc[];
    const int tid = threadIdx.x;
    u64* W1T = (u64*)(smc + OFF_MW1T);
    u64* W2T = (u64*)(smc + OFF_MW2T);
    float* B1S = (float*)(smc + OFF_MB1);
    float* B2S = (float*)(smc + OFF_MB2);
    for (int i = tid; i < 128*64; i += 384) {
        int n = i >> 6, p = i & 63;
        W1T[n*64 + (p ^ ((n&3)<<2))] = split4(We1[(2*p)*128 + n], We1[(2*p+1)*128 + n]);
    }
    for (int i = tid; i < 64*64; i += 384) {
        int n = i >> 6, p = i & 63;
        W2T[n*64 + (p ^ ((n&3)<<2))] = split4(We2[(2*p)*64 + n], We2[(2*p+1)*64 + n]);
    }
    if (tid < 128) B1S[tid] = be1[tid];
    else if (tid < 192) B2S[tid-128] = be2[tid-128];
    __syncthreads();

    const int warp = tid >> 5, lane = tid & 31;
    const int g = lane >> 2, tg = lane & 3;
    const int sw = (g & 3) << 2;
    u64* XI = (u64*)(smc + OFF_MX) + warp*1024;
    const int rows = NEDGE;

    for (int tile = blockIdx.x; tile < TET; tile += gridDim.x) {
        const int row0 = tile * TRW;
        const int wrow0 = row0 + warp*16;
        const bool full = (row0 + TRW <= rows);

        #pragma unroll
        for (int r = 0; r < 16; r++) {
            int gr = wrow0 + r;
            int rs = (r & 3) << 2;
            float2 v0 = make_float2(0.f, 0.f);
            float2 v1 = make_float2(0.f, 0.f);
            if (full || gr < rows) {
                v0 = *(const float2*)&edge[(size_t)gr*64 + lane*2];
                int4 ix = *(const int4*)&c2e[gr*4];
                float2 a = *(const float2*)&cycout[(size_t)ix.x*64 + lane*2];
                float2 b = *(const float2*)&cycout[(size_t)ix.y*64 + lane*2];
                float2 c = *(const float2*)&cycout[(size_t)ix.z*64 + lane*2];
                float2 dd = *(const float2*)&cycout[(size_t)ix.w*64 + lane*2];
                v1.x = a.x + b.x + c.x + dd.x;
                v1.y = a.y + b.y + c.y + dd.y;
            }
            XI[r*64 + (lane ^ rs)]        = split4(v0.x, v0.y);
            XI[r*64 + ((32 + lane) ^ rs)] = split4(v1.x, v1.y);
        }
        __syncwarp();

        const int ga = wrow0 + g, gb = wrow0 + g + 8;

        // ---------- h = relu(in @ We1 + be1) : K=128 ----------
        float d[16][4];
        #pragma unroll
        for (int j = 0; j < 16; j++) {
            float2 bb = *(const float2*)&B1S[j*8 + 2*tg];
            d[j][0] = bb.x; d[j][1] = bb.y; d[j][2] = bb.x; d[j][3] = bb.y;
        }
        for (int kk = 0; kk < 128; kk += 16) {
            int p0 = (kk >> 1) + tg;
            int c0 = p0 ^ sw, c1 = (p0 + 4) ^ sw;
            u64 t0 = XI[g*64     + c0];
            u64 t1 = XI[(g+8)*64 + c0];
            u64 t2 = XI[g*64     + c1];
            u64 t3 = XI[(g+8)*64 + c1];
            u32 ah0 = (u32)t0, al0 = (u32)(t0 >> 32);
            u32 ah1 = (u32)t1, al1 = (u32)(t1 >> 32);
            u32 ah2 = (u32)t2, al2 = (u32)(t2 >> 32);
            u32 ah3 = (u32)t3, al3 = (u32)(t3 >> 32);
            #pragma unroll
            for (int j = 0; j < 16; j++) {
                int n = j*8 + g;
                u64 w0 = W1T[n*64 + c0];
                u64 w1 = W1T[n*64 + c1];
                u32 bh0 = (u32)w0, bl0 = (u32)(w0 >> 32);
                u32 bh1 = (u32)w1, bl1 = (u32)(w1 >> 32);
                mma_bf16(d[j], ah0, ah1, ah2, ah3, bh0, bh1);
                mma_bf16(d[j], ah0, ah1, ah2, ah3, bl0, bl1);
                mma_bf16(d[j], al0, al1, al2, al3, bh0, bh1);
            }
        }
        u64 ph[16][2];
        #pragma unroll
        for (int j = 0; j < 16; j++) {
            ph[j][0] = split4(fmaxf(d[j][0], 0.f), fmaxf(d[j][1], 0.f));
            ph[j][1] = split4(fmaxf(d[j][2], 0.f), fmaxf(d[j][3], 0.f));
        }

        // ---------- out = h @ We2 + be2 (no relu) : K=128, A from regs ----------
        float e[8][4];
        #pragma unroll
        for (int j = 0; j < 8; j++) {
            float2 bb = *(const float2*)&B2S[j*8 + 2*tg];
            e[j][0] = bb.x; e[j][1] = bb.y; e[j][2] = bb.x; e[j][3] = bb.y;
        }
        #pragma unroll
        for (int kk = 0; kk < 128; kk += 16) {
            int jj = kk >> 3;
            int p0 = (kk >> 1) + tg;
            int c0 = p0 ^ sw, c1 = (p0 + 4) ^ sw;
            u64 t0 = ph[jj][0];
            u64 t1 = ph[jj][1];
            u64 t2 = ph[jj+1][0];
            u64 t3 = ph[jj+1][1];
            u32 ah0 = (u32)t0, al0 = (u32)(t0 >> 32);
            u32 ah1 = (u32)t1, al1 = (u32)(t1 >> 32);
            u32 ah2 = (u32)t2, al2 = (u32)(t2 >> 32);
            u32 ah3 = (u32)t3, al3 = (u32)(t3 >> 32);
            #pragma unroll
            for (int j = 0; j < 8; j++) {
                int n = j*8 + g;
                u64 w0 = W2T[n*64 + c0];
                u64 w1 = W2T[n*64 + c1];
                u32 bh0 = (u32)w0, bl0 = (u32)(w0 >> 32);
                u32 bh1 = (u32)w1, bl1 = (u32)(w1 >> 32);
                mma_bf16(e[j], ah0, ah1, ah2, ah3, bh0, bh1);
                mma_bf16(e[j], ah0, ah1, ah2, ah3, bl0, bl1);
                mma_bf16(e[j], al0, al1, al2, al3, bh0, bh1);
            }
        }
        if (full) {
            #pragma unroll
            for (int j = 0; j < 8; j++) {
                *(float2*)&outp[(size_t)ga*64 + j*8 + 2*tg] = make_float2(e[j][0], e[j][1]);
                *(float2*)&outp[(size_t)gb*64 + j*8 + 2*tg] = make_float2(e[j][2], e[j][3]);
            }
        } else {
            #pragma unroll
            for (int j = 0; j < 8; j++) {
                if (ga < rows) *(float2*)&outp[(size_t)ga*64 + j*8 + 2*tg] = make_float2(e[j][0], e[j][1]);
                if (gb < rows) *(float2*)&outp[(size_t)gb*64 + j*8 + 2*tg] = make_float2(e[j][2], e[j][3]);
            }
        }
        __syncwarp();
    }
}

// ---------------- launch ----------------
extern "C" void kernel_launch(void* const* d_in, const int* in_sizes, int n_in,
                              void* d_out, int out_size)
{
    const float* edge_rep = (const float*)d_in[0];
    const float* cyc5 = (const float*)d_in[1];
    const float* cyc6 = (const float*)d_in[2];
    const int*   e2c5 = (const int*)d_in[3];
    const int*   e2c6 = (const int*)d_in[4];
    const int*   c2e  = (const int*)d_in[5];
    const float* W1  = (const float*)d_in[6];
    const float* b1  = (const float*)d_in[7];
    const float* W2  = (const float*)d_in[8];
    const float* b2  = (const float*)d_in[9];
    const float* Wc1 = (const float*)d_in[10];
    const float* bc1 = (const float*)d_in[11];
    const float* Wc2 = (const float*)d_in[12];
    const float* bc2 = (const float*)d_in[13];
    const float* Wc3 = (const float*)d_in[14];
    const float* bc3 = (const float*)d_in[15];
    const float* We1 = (const float*)d_in[16];
    const float* be1 = (const float*)d_in[17];
    const float* We2 = (const float*)d_in[18];
    const float* be2 = (const float*)d_in[19];
    const float* Wid5  = (const float*)d_in[20];
    const float* Wsum5 = (const float*)d_in[21];
    const float* bab5  = (const float*)d_in[22];
    const float* Wid6  = (const float*)d_in[23];
    const float* Wsum6 = (const float*)d_in[24];
    const float* bab6  = (const float*)d_in[25];
    float* out = (float*)d_out;

    float *x5, *x6, *sB5, *sB6, *A5, *B5, *c5, *A6, *B6, *c6;
    cudaGetSymbolAddress((void**)&x5,  g_x5);
    cudaGetSymbolAddress((void**)&x6,  g_x6);
    cudaGetSymbolAddress((void**)&sB5, g_sB5);
    cudaGetSymbolAddress((void**)&sB6, g_sB6);
    cudaGetSymbolAddress((void**)&A5,  g_A5);
    cudaGetSymbolAddress((void**)&B5,  g_B5);
    cudaGetSymbolAddress((void**)&c5,  g_c5);
    cudaGetSymbolAddress((void**)&A6,  g_A6);
    cudaGetSymbolAddress((void**)&B6,  g_B6);
    cudaGetSymbolAddress((void**)&c6,  g_c6);

    cudaFuncSetAttribute(mlp2_kernel, cudaFuncAttributeMaxDynamicSharedMemorySize, SMEM_MT);
    cudaFuncSetAttribute(edge_kernel, cudaFuncAttributeMaxDynamicSharedMemorySize, SMEM_MT);
    cudaFuncSetAttribute(cyc2_kernel, cudaFuncAttributeMaxDynamicSharedMemorySize, SMEM_CYC2T);
    cudaFuncSetAttribute(sB_kernel,   cudaFuncAttributeMaxDynamicSharedMemorySize, SMEM_SB);

    const int NBLK = 152;

    fold_all_kernel<<<130, 128>>>(Wc1, bc1, Wid5, Wsum5, bab5, Wid6, Wsum6, bab6,
                                  A5, B5, c5, A6, B6, c6);

    mlp2_kernel<<<NBLK, 384, SMEM_MT>>>(cyc5, e2c5, cyc6, e2c6, edge_rep,
                                        W1, b1, W2, b2, x5, x6);

    sB_kernel<<<NBLK, 512, SMEM_SB>>>(x5, x6, B5, c5, B6, c6, sB5, sB6);

    cyc2_kernel<<<NBLK, 384, SMEM_CYC2T>>>(x5, sB5, A5, x6, sB6, A6,
                                           Wc2, bc2, Wc3, bc3,
                                           out + (size_t)NEDGE*64);

    edge_kernel<<<NBLK, 384, SMEM_MT>>>(edge_rep, c2e, out + (size_t)NEDGE*64,
                                        We1, be1, We2, be2, out);
}